// round 13
// baseline (speedup 1.0000x reference)
#include <cuda_runtime.h>
#include <cuda_fp16.h>
#include <math.h>
#include <stdint.h>

// Problem constants
#define Bsz  4096
#define Dd   256
#define Hh   256
#define Ss   3
#define REPT 10
#define OUTN 44
#define SH   768      // S*H
#define NZS  1024     // Z rows: f,i,o,c blocks of 256
#define NU   768
#define NAG  2304     // fused AG: 3 layers x 768 aux rows
#define FEATK 2304    // (REP-1)*H

// ---------------- scratch (static device arrays; no cudaMalloc) ------------
__device__ __half g_hsp[(size_t)Bsz * SH];        // fp16 hidden state (h_cat layout)
__device__ float  g_hf[(size_t)Bsz * SH];         // fp32 h_cat copy
__device__ __half g_xsp[(size_t)Bsz * Dd];        // fp16 x
__device__ float  g_c[(size_t)Bsz * SH];
__device__ __half g_U[(size_t)Ss * Bsz * NU];     // fp16 preacts
__device__ __half g_AG[(size_t)Bsz * NAG];        // fp16 preacts
__device__ float  g_G2[(size_t)Bsz * 12];         // Wh_g . h_cat + bh_g (9 used)
__device__ float  g_G0[(size_t)Bsz * 3];          // Wi_g[0] . x + bi_g[0]
__device__ __half g_Z[(size_t)Bsz * NZS];         // fp16 preacts
__device__ __half g_Z0[(size_t)Bsz * NZS];
__device__ float  g_featf[(size_t)Bsz * FEATK];
__device__ __half g_WiAll[(size_t)Ss * NZS * Dd];
__device__ float  g_biAll[Ss * NZS];
__device__ __half g_Whfio[(size_t)Ss * NU * Hh];
__device__ float  g_bhfio[Ss * NU];
__device__ __half g_Whc[(size_t)NAG * SH];

__device__ __forceinline__ float sigf(float x) { return 1.0f / (1.0f + expf(-x)); }

// ---------------- fp16 HMMA GEMM core: 128x128x64, 2 CTAs/SM ----------------
#define BM 128
#define BN 128
#define BKE 64
#define SAS 72
#define SA_SZ (BM * SAS)            // 9216 elems
#define SB_SZ (BN * SAS)            // 9216 elems
#define STG_E (SA_SZ + SB_SZ)       // 18432 elems
#define SMEM_GEMM (3 * STG_E * 2)   // 110592 bytes -> 2 CTAs/SM

#define LDSM4(r0,r1,r2,r3,addr) \
  asm volatile("ldmatrix.sync.aligned.m8n8.x4.shared.b16 {%0,%1,%2,%3}, [%4];" \
   : "=r"(r0),"=r"(r1),"=r"(r2),"=r"(r3) : "r"(addr))

#define MMA16816(d, a, b) \
  asm volatile("mma.sync.aligned.m16n8k16.row.col.f32.f16.f16.f32 " \
    "{%0,%1,%2,%3}, {%4,%5,%6,%7}, {%8,%9}, {%0,%1,%2,%3};" \
    : "+f"(d[0]),"+f"(d[1]),"+f"(d[2]),"+f"(d[3]) \
    : "r"(a[0]),"r"(a[1]),"r"(a[2]),"r"(a[3]), "r"(b[0]),"r"(b[1]))

// warp layout: 8 warps, wm = warp&1 (2 x 64 rows), wn = warp>>1 (4 x 32 cols)
__device__ __forceinline__ void
gemm_main(const __half* __restrict__ A, int lda,
          const __half* __restrict__ W, int ldw,
          int m0, int n0, int K, float acw[4][4][4])
{
    extern __shared__ __align__(16) __half smem[];
    const int tid  = threadIdx.x;
    const int warp = tid >> 5;
    const int lane = tid & 31;
    const int wm = warp & 1;
    const int wn = warp >> 1;
    const int KT = K / BKE;

#pragma unroll
    for (int mi = 0; mi < 4; mi++)
#pragma unroll
        for (int ni = 0; ni < 4; ni++)
#pragma unroll
            for (int q = 0; q < 4; q++) acw[mi][ni][q] = 0.f;

    auto load_tiles = [&](int kt, int s) {
        const __half* Ap = A + kt * BKE;
        const __half* Wp = W + kt * BKE;
        __half* sa0 = smem + s * STG_E;
        __half* sb0 = sa0 + SA_SZ;
#pragma unroll
        for (int i = 0; i < 4; i++) {           // A: 128 rows x 8 chunks of 16B
            int idx = tid + i * 256;
            int row = idx >> 3;
            int ch  = idx & 7;
            unsigned sa = (unsigned)__cvta_generic_to_shared(&sa0[row * SAS + ch * 8]);
            const void* ga = Ap + (size_t)(m0 + row) * lda + ch * 8;
            asm volatile("cp.async.cg.shared.global [%0], [%1], 16;" :: "r"(sa), "l"(ga));
        }
#pragma unroll
        for (int i = 0; i < 4; i++) {           // B: 128 rows x 8 chunks
            int idx = tid + i * 256;
            int row = idx >> 3;
            int ch  = idx & 7;
            unsigned sb = (unsigned)__cvta_generic_to_shared(&sb0[row * SAS + ch * 8]);
            const void* gw = Wp + (size_t)(n0 + row) * ldw + ch * 8;
            asm volatile("cp.async.cg.shared.global [%0], [%1], 16;" :: "r"(sb), "l"(gw));
        }
        asm volatile("cp.async.commit_group;");
    };

    load_tiles(0, 0);
    load_tiles(1, 1);

    const int lt  = lane >> 3;
    const int lr  = lane & 7;

    int s = 0;
    for (int kt = 0; kt < KT; kt++) {
        asm volatile("cp.async.wait_group 1;");
        __syncthreads();

        const __half* pa = smem + s * STG_E;
        const __half* pb = pa + SA_SZ;
#pragma unroll
        for (int kq = 0; kq < 4; kq++) {
            const int k0 = kq * 16;
            unsigned af[4][4];
#pragma unroll
            for (int mi = 0; mi < 4; mi++) {
                int mrow = wm * 64 + mi * 16 + (lt & 1) * 8 + lr;
                int kcol = k0 + (lt >> 1) * 8;
                unsigned addr = (unsigned)__cvta_generic_to_shared(&pa[mrow * SAS + kcol]);
                LDSM4(af[mi][0], af[mi][1], af[mi][2], af[mi][3], addr);
            }
            unsigned bf[4][2];
#pragma unroll
            for (int nb = 0; nb < 2; nb++) {
                int nrow = wn * 32 + nb * 16 + (lt >> 1) * 8 + lr;
                int kcol = k0 + (lt & 1) * 8;
                unsigned addr = (unsigned)__cvta_generic_to_shared(&pb[nrow * SAS + kcol]);
                unsigned r0, r1, r2, r3;
                LDSM4(r0, r1, r2, r3, addr);
                bf[nb * 2][0] = r0;     bf[nb * 2][1] = r1;
                bf[nb * 2 + 1][0] = r2; bf[nb * 2 + 1][1] = r3;
            }
#pragma unroll
            for (int mi = 0; mi < 4; mi++)
#pragma unroll
                for (int ni = 0; ni < 4; ni++)
                    MMA16816(acw[mi][ni], af[mi], bf[ni]);
        }
        if (kt + 2 < KT) load_tiles(kt + 2, (s + 2 >= 3) ? s - 1 : s + 2);
        else asm volatile("cp.async.commit_group;");
        if (++s == 3) s = 0;
    }
}

// epilogue: fp32 accum + fp32 bias -> fp16 store (half2 pairs)
__device__ __forceinline__ void
gemm_epi_store(float acw[4][4][4], const float* __restrict__ bz,
               __half* __restrict__ C, int ldc, int m0, int n0)
{
    const int warp = threadIdx.x >> 5;
    const int lane = threadIdx.x & 31;
    const int wm = warp & 1;
    const int wn = warp >> 1;
#pragma unroll
    for (int mi = 0; mi < 4; mi++) {
        const int r0 = m0 + wm * 64 + mi * 16 + (lane >> 2);
#pragma unroll
        for (int ni = 0; ni < 4; ni++) {
            const int cc = n0 + wn * 32 + ni * 8 + (lane & 3) * 2;
            const float* a = acw[mi][ni];
            float b0 = bz[cc], b1 = bz[cc + 1];
            *(__half2*)&C[(size_t)r0 * ldc + cc] =
                __floats2half2_rn(a[0] + b0, a[1] + b1);
            *(__half2*)&C[(size_t)(r0 + 8) * ldc + cc] =
                __floats2half2_rn(a[2] + b0, a[3] + b1);
        }
    }
}

__global__ void __launch_bounds__(256, 2)
gemm256(const __half* __restrict__ A, int lda,
        const __half* __restrict__ W, int ldw,
        const float* __restrict__ bias,
        __half* __restrict__ C, int ldc, int K)
{
    float acw[4][4][4];
    gemm_main(A, lda, W, ldw, blockIdx.y * BM, blockIdx.x * BN, K, acw);
    gemm_epi_store(acw, bias, C, ldc, blockIdx.y * BM, blockIdx.x * BN);
}

// Combined AG + U + G2 launch: grid (19, 32, 2).
//   z=0, x<18 : AG tile.  z=1, x<18 : U tile (l=x/6, nt=x%6).  z=1, x==18 : G2.
__global__ void __launch_bounds__(256, 2)
gemm_agu(const __half* __restrict__ hsp,
         const __half* __restrict__ Whc, const float* __restrict__ bhc,
         __half* __restrict__ AG,
         const __half* __restrict__ Whfio, const float* __restrict__ bhfio,
         __half* __restrict__ U,
         const float* __restrict__ hf, const float* __restrict__ whg,
         const float* __restrict__ bhg, float* __restrict__ G2)
{
    if (blockIdx.z == 0) {
        if (blockIdx.x >= 18) return;
        float acw[4][4][4];
        gemm_main(hsp, SH, Whc, SH, blockIdx.y * BM, blockIdx.x * BN, SH, acw);
        gemm_epi_store(acw, bhc, AG, NAG, blockIdx.y * BM, blockIdx.x * BN);
    } else if (blockIdx.x < 18) {
        const int l  = blockIdx.x / 6;
        const int xt = blockIdx.x - l * 6;
        float acw[4][4][4];
        gemm_main(hsp + l * Hh, SH, Whfio + (size_t)l * NU * Hh, Hh,
                  blockIdx.y * BM, xt * BN, Hh, acw);
        gemm_epi_store(acw, bhfio + l * NU, U + (size_t)l * Bsz * NU, NU,
                       blockIdx.y * BM, xt * BN);
    } else {
        // G2: 9 dots of 768 per row (reads h_cat(t-1)), 128 rows per m-tile
        const int m0 = blockIdx.y * BM;
        const int warp = threadIdx.x >> 5;
        const int lane = threadIdx.x & 31;
        for (int rr = 0; rr < 16; rr++) {
            int row = m0 + warp * 16 + rr;
            const float* hr = hf + (size_t)row * SH;
            float p[9];
#pragma unroll
            for (int o = 0; o < 9; o++) p[o] = 0.f;
            for (int i = 0; i < 24; i++) {
                int k = lane + 32 * i;
                float hv = hr[k];
#pragma unroll
                for (int o = 0; o < 9; o++) p[o] += hv * whg[o * SH + k];
            }
#pragma unroll
            for (int o = 0; o < 9; o++) {
#pragma unroll
                for (int off = 16; off; off >>= 1)
                    p[o] += __shfl_xor_sync(0xFFFFFFFFu, p[o], off);
            }
            if (lane == 0) {
#pragma unroll
                for (int o = 0; o < 9; o++)
                    G2[(size_t)row * 12 + o] = p[o] + bhg[o];
            }
        }
    }
}

// ---------------- per-layer LSTM cell (block = one batch row) ---------------
__global__ void __launch_bounds__(256)
cell_kernel(const __half* __restrict__ Z, const __half* __restrict__ U,
            const __half* __restrict__ AG, const float* __restrict__ G2,
            const float* __restrict__ G0,
            const float* __restrict__ wig3, const float* __restrict__ big3,
            const float* __restrict__ hin,
            __half* __restrict__ hsp, float* __restrict__ hf,
            float* __restrict__ c, float* __restrict__ featf, int l, int t)
{
    const int b = blockIdx.x;
    const int j = threadIdx.x;
    const int warp = j >> 5;
    const int lane = j & 31;
    __shared__ float red[3][8];

    float gin0, gin1, gin2;
    if (l == 0) {
        gin0 = G0[(size_t)b * 3 + 0];
        gin1 = G0[(size_t)b * 3 + 1];
        gin2 = G0[(size_t)b * 3 + 2];
    } else {
        float iv = hin[(size_t)b * SH + j];
        float p0 = iv * wig3[j];
        float p1 = iv * wig3[256 + j];
        float p2 = iv * wig3[512 + j];
#pragma unroll
        for (int off = 16; off; off >>= 1) {
            p0 += __shfl_xor_sync(0xFFFFFFFFu, p0, off);
            p1 += __shfl_xor_sync(0xFFFFFFFFu, p1, off);
            p2 += __shfl_xor_sync(0xFFFFFFFFu, p2, off);
        }
        if (lane == 0) { red[0][warp] = p0; red[1][warp] = p1; red[2][warp] = p2; }
        __syncthreads();
        float s0 = 0.f, s1 = 0.f, s2 = 0.f;
#pragma unroll
        for (int w = 0; w < 8; w++) { s0 += red[0][w]; s1 += red[1][w]; s2 += red[2][w]; }
        gin0 = s0 + big3[0];
        gin1 = s1 + big3[1];
        gin2 = s2 + big3[2];
    }

    const float* g2p = G2 + (size_t)b * 12 + l * 3;
    float g0 = sigf(gin0 + g2p[0]);
    float g1 = sigf(gin1 + g2p[1]);
    float g2v = sigf(gin2 + g2p[2]);

    const __half* Zb = Z + (size_t)b * NZS;
    const __half* Ub = U + (size_t)b * NU;
    const __half* Gb = AG + (size_t)b * NAG + l * SH;
    float aux = g0 * __half2float(Gb[j]) + g1 * __half2float(Gb[256 + j])
              + g2v * __half2float(Gb[512 + j]);

    float fg = sigf(__half2float(Zb[j])       + __half2float(Ub[j]));
    float ig = sigf(__half2float(Zb[256 + j]) + __half2float(Ub[256 + j]));
    float og = sigf(__half2float(Zb[512 + j]) + __half2float(Ub[512 + j]));
    float ct = tanhf(__half2float(Zb[768 + j]) + aux);

    size_t sidx = (size_t)b * SH + l * Hh + j;
    float cn = fg * c[sidx] + ig * ct;
    float hn = og * cn;
    c[sidx] = cn;
    hf[sidx] = hn;
    hsp[sidx] = __float2half(hn);
    if (featf) featf[(size_t)b * FEATK + t * Hh + j] = hn;
}

// ---------------- small fp32 dot kernels ------------------------------------
__global__ void glog0_kernel(const float* __restrict__ x,
                             const float* __restrict__ wig,
                             const float* __restrict__ big,
                             float* __restrict__ G0)
{
    int gw = (blockIdx.x * blockDim.x + threadIdx.x) >> 5;
    int lane = threadIdx.x & 31;
    if (gw >= Bsz * 3) return;
    int b = gw / 3;
    int r = gw - b * 3;
    const float* xr = x + (size_t)b * Dd;
    const float* wr = wig + (size_t)r * Dd;
    float sum = 0.f;
#pragma unroll 4
    for (int k = lane; k < Dd; k += 32) sum += xr[k] * wr[k];
#pragma unroll
    for (int off = 16; off; off >>= 1) sum += __shfl_xor_sync(0xFFFFFFFFu, sum, off);
    if (lane == 0) G0[(size_t)b * 3 + r] = sum + big[r];
}

__global__ void out_kernel(const float* __restrict__ featf,
                           const float* __restrict__ wl,
                           const float* __restrict__ bl,
                           float* __restrict__ out)
{
    int gw = (blockIdx.x * blockDim.x + threadIdx.x) >> 5;
    int lane = threadIdx.x & 31;
    if (gw >= Bsz * OUTN) return;
    int b = gw / OUTN;
    int o = gw - b * OUTN;
    const float* fr = featf + (size_t)b * FEATK;
    const float* wr = wl + (size_t)o * FEATK;
    float sum = 0.f;
#pragma unroll 8
    for (int k = lane; k < FEATK; k += 32) sum += fr[k] * wr[k];
#pragma unroll
    for (int off = 16; off; off >>= 1) sum += __shfl_xor_sync(0xFFFFFFFFu, sum, off);
    if (lane == 0) out[(size_t)b * OUTN + o] = sigf(sum + bl[o]);
}

// ---------------- state init / splits --------------------------------------
__global__ void init_state(const float* __restrict__ hid, const float* __restrict__ cur,
                           __half* __restrict__ hsp, float* __restrict__ hf,
                           float* __restrict__ c)
{
    int i = blockIdx.x * blockDim.x + threadIdx.x;
    const int total = Ss * Bsz * Hh;
    if (i >= total) return;
    int l = i / (Bsz * Hh);
    int r = i - l * (Bsz * Hh);
    int b = r >> 8;
    int j = r & 255;
    float v = hid[i];
    size_t dst = (size_t)b * SH + l * Hh + j;
    hsp[dst] = __float2half(v);
    hf[dst]  = v;
    c[dst]   = cur[i];
}

__global__ void conv_x(const float* __restrict__ x, __half* __restrict__ xsp)
{
    int i = blockIdx.x * blockDim.x + threadIdx.x;
    if (i >= Bsz * Dd) return;
    xsp[i] = __float2half(x[i]);
}

// ---------------- fused weight repack (fp32 -> fp16, concat rows) ----------
#define RW1 (Ss * NZS * Dd)
#define RW2 (RW1 + Ss * NU * Hh)
#define RW3 (RW2 + NAG * SH)
#define RW4 (RW3 + Ss * NZS)
#define RW5 (RW4 + Ss * NU)

__global__ void repack_all(const float* __restrict__ wif, const float* __restrict__ wii,
                           const float* __restrict__ wio, const float* __restrict__ wic,
                           const float* __restrict__ whf, const float* __restrict__ whi,
                           const float* __restrict__ who, const float* __restrict__ whc,
                           const float* __restrict__ bif, const float* __restrict__ bii,
                           const float* __restrict__ bio, const float* __restrict__ bic,
                           const float* __restrict__ bhf, const float* __restrict__ bhi,
                           const float* __restrict__ bho,
                           __half* __restrict__ WiAll, __half* __restrict__ Whfio,
                           __half* __restrict__ Whc,
                           float* __restrict__ biAll, float* __restrict__ bhfio)
{
    int idx = blockIdx.x * blockDim.x + threadIdx.x;
    if (idx < RW1) {
        int k = idx % Dd;
        int r = (idx / Dd) % NZS;
        int l = idx / (Dd * NZS);
        float v;
        if      (r < 256) v = wif[((size_t)l * Hh + r)       * Dd + k];
        else if (r < 512) v = wii[((size_t)l * Hh + r - 256) * Dd + k];
        else if (r < 768) v = wio[((size_t)l * Hh + r - 512) * Dd + k];
        else              v = wic[((size_t)l * Hh + r - 768) * Dd + k];
        WiAll[idx] = __float2half(v);
    } else if (idx < RW2) {
        int t = idx - RW1;
        int k = t % Hh;
        int r = (t / Hh) % NU;
        int l = t / (Hh * NU);
        float v;
        if      (r < 256) v = whf[((size_t)l * Hh + r)       * Hh + k];
        else if (r < 512) v = whi[((size_t)l * Hh + r - 256) * Hh + k];
        else              v = who[((size_t)l * Hh + r - 512) * Hh + k];
        Whfio[t] = __float2half(v);
    } else if (idx < RW3) {
        int t = idx - RW2;
        Whc[t] = __float2half(whc[t]);
    } else if (idx < RW4) {
        int t = idx - RW3;
        int r = t % NZS, l = t / NZS;
        float v;
        if      (r < 256) v = bif[l * Hh + r];
        else if (r < 512) v = bii[l * Hh + r - 256];
        else if (r < 768) v = bio[l * Hh + r - 512];
        else              v = bic[l * Hh + r - 768];
        biAll[t] = v;
    } else if (idx < RW5) {
        int t = idx - RW4;
        int r = t % NU, l = t / NU;
        float v;
        if      (r < 256) v = bhf[l * Hh + r];
        else if (r < 512) v = bhi[l * Hh + r - 256];
        else              v = bho[l * Hh + r - 512];
        bhfio[t] = v;
    }
}

// ---------------- orchestration --------------------------------------------
extern "C" void kernel_launch(void* const* d_in, const int* in_sizes, int n_in,
                              void* d_out, int out_size)
{
    (void)in_sizes; (void)n_in; (void)out_size;
    const float* x    = (const float*)d_in[0];
    const float* hid0 = (const float*)d_in[1];
    const float* cur0 = (const float*)d_in[2];
    const float* Wi_f = (const float*)d_in[3];
    const float* bi_f = (const float*)d_in[4];
    const float* Wi_i = (const float*)d_in[5];
    const float* bi_i = (const float*)d_in[6];
    const float* Wi_o = (const float*)d_in[7];
    const float* bi_o = (const float*)d_in[8];
    const float* Wi_c = (const float*)d_in[9];
    const float* bi_c = (const float*)d_in[10];
    const float* Wi_g = (const float*)d_in[11];
    const float* bi_g = (const float*)d_in[12];
    const float* Wh_f = (const float*)d_in[13];
    const float* bh_f = (const float*)d_in[14];
    const float* Wh_i = (const float*)d_in[15];
    const float* bh_i = (const float*)d_in[16];
    const float* Wh_o = (const float*)d_in[17];
    const float* bh_o = (const float*)d_in[18];
    const float* Wh_g = (const float*)d_in[19];
    const float* bh_g = (const float*)d_in[20];
    const float* Wh_c = (const float*)d_in[21];
    const float* bh_c = (const float*)d_in[22];
    const float* W_last = (const float*)d_in[23];
    const float* b_last = (const float*)d_in[24];
    float* out = (float*)d_out;

    __half *hsp, *xsp, *WiAll, *Whfio, *Whc, *U, *AG, *Z, *Z0;
    float *hf, *c, *G2, *G0, *featf, *biAll, *bhfio;
    cudaGetSymbolAddress((void**)&hsp,   g_hsp);
    cudaGetSymbolAddress((void**)&hf,    g_hf);
    cudaGetSymbolAddress((void**)&xsp,   g_xsp);
    cudaGetSymbolAddress((void**)&c,     g_c);
    cudaGetSymbolAddress((void**)&U,     g_U);
    cudaGetSymbolAddress((void**)&AG,    g_AG);
    cudaGetSymbolAddress((void**)&G2,    g_G2);
    cudaGetSymbolAddress((void**)&G0,    g_G0);
    cudaGetSymbolAddress((void**)&Z,     g_Z);
    cudaGetSymbolAddress((void**)&Z0,    g_Z0);
    cudaGetSymbolAddress((void**)&featf, g_featf);
    cudaGetSymbolAddress((void**)&WiAll, g_WiAll);
    cudaGetSymbolAddress((void**)&biAll, g_biAll);
    cudaGetSymbolAddress((void**)&Whfio, g_Whfio);
    cudaGetSymbolAddress((void**)&bhfio, g_bhfio);
    cudaGetSymbolAddress((void**)&Whc,   g_Whc);

    cudaFuncSetAttribute(gemm256,  cudaFuncAttributeMaxDynamicSharedMemorySize, SMEM_GEMM);
    cudaFuncSetAttribute(gemm_agu, cudaFuncAttributeMaxDynamicSharedMemorySize, SMEM_GEMM);

    const dim3 blk(256);

    // ---- setup ----
    init_state<<<(Ss * Bsz * Hh + 255) / 256, blk>>>(hid0, cur0, hsp, hf, c);
    conv_x<<<(Bsz * Dd + 255) / 256, blk>>>(x, xsp);
    repack_all<<<(RW5 + 255) / 256, blk>>>(Wi_f, Wi_i, Wi_o, Wi_c,
                                           Wh_f, Wh_i, Wh_o, Wh_c,
                                           bi_f, bi_i, bi_o, bi_c,
                                           bh_f, bh_i, bh_o,
                                           WiAll, Whfio, Whc, biAll, bhfio);
    glog0_kernel<<<(Bsz * 3 * 32 + 255) / 256, blk>>>(x, Wi_g, bi_g, G0);
    // Z0 = x @ Wi[0]^T + bias  (time-invariant)
    gemm256<<<dim3(8, 32, 1), blk, SMEM_GEMM>>>(xsp, Dd, WiAll, Dd,
                                                biAll, Z0, NZS, Dd);

    for (int t = 0; t < REPT; t++) {
        // AG + U + G2 (all read state(t-1))
        gemm_agu<<<dim3(19, 32, 2), blk, SMEM_GEMM>>>(hsp, Whc, bh_c, AG,
                                                      Whfio, bhfio, U,
                                                      hf, Wh_g, bh_g, G2);
        // cell0
        cell_kernel<<<Bsz, blk>>>(Z0, U, AG, G2, G0,
                                  nullptr, nullptr, nullptr,
                                  hsp, hf, c, nullptr, 0, t);
        // Z1
        gemm256<<<dim3(8, 32, 1), blk, SMEM_GEMM>>>(
            hsp, SH, WiAll + (size_t)NZS * Dd, Dd,
            biAll + NZS, Z, NZS, Hh);
        // cell1
        cell_kernel<<<Bsz, blk>>>(Z, U + (size_t)Bsz * NU, AG, G2, nullptr,
                                  Wi_g + (size_t)3 * Dd, bi_g + 3, hf,
                                  hsp, hf, c, nullptr, 1, t);
        // Z2
        gemm256<<<dim3(8, 32, 1), blk, SMEM_GEMM>>>(
            hsp + Hh, SH, WiAll + (size_t)2 * NZS * Dd, Dd,
            biAll + 2 * NZS, Z, NZS, Hh);
        // cell2
        float* fptr = (t < REPT - 1) ? featf : nullptr;
        cell_kernel<<<Bsz, blk>>>(Z, U + (size_t)2 * Bsz * NU, AG, G2, nullptr,
                                  Wi_g + (size_t)6 * Dd, bi_g + 6, hf + Hh,
                                  hsp, hf, c, fptr, 2, t);
    }

    out_kernel<<<(Bsz * OUTN * 32 + 255) / 256, blk>>>(featf, W_last, b_last, out);
}

// round 14
// speedup vs baseline: 1.1604x; 1.1604x over previous
#include <cuda_runtime.h>
#include <cuda_fp16.h>
#include <math.h>
#include <stdint.h>

// Problem constants
#define Bsz  4096
#define Dd   256
#define Hh   256
#define Ss   3
#define REPT 10
#define OUTN 44
#define SH   768      // S*H
#define NZS  1024     // Z rows: f,i,o,c blocks of 256
#define NU   768
#define NAG  2304     // fused AG: 3 layers x 768 aux rows
#define FEATK 2304    // (REP-1)*H

// ---------------- scratch (static device arrays; no cudaMalloc) ------------
__device__ __half g_hsp[(size_t)Bsz * SH];        // fp16 hidden state (h_cat layout)
__device__ float  g_hf[(size_t)Bsz * SH];         // fp32 h_cat copy
__device__ __half g_xsp[(size_t)Bsz * Dd];        // fp16 x
__device__ float  g_c[(size_t)Bsz * SH];
__device__ __half g_U[(size_t)Ss * Bsz * NU];     // fp16 preacts
__device__ __half g_AG[(size_t)Bsz * NAG];        // fp16 preacts
__device__ float  g_G2[(size_t)Bsz * 12];         // Wh_g . h_cat + bh_g (9 used)
__device__ float  g_G0[(size_t)Bsz * 3];          // Wi_g[0] . x + bi_g[0]
__device__ __half g_Z[(size_t)Bsz * NZS];         // fp16 preacts
__device__ __half g_Z0[(size_t)Bsz * NZS];
__device__ float  g_featf[(size_t)Bsz * FEATK];
__device__ __half g_WiAll[(size_t)Ss * NZS * Dd];
__device__ float  g_biAll[Ss * NZS];
__device__ __half g_Whfio[(size_t)Ss * NU * Hh];
__device__ float  g_bhfio[Ss * NU];
__device__ __half g_Whc[(size_t)NAG * SH];

__device__ __forceinline__ float sigf(float x) { return 1.0f / (1.0f + expf(-x)); }

// ---------------- PDL intrinsics --------------------------------------------
__device__ __forceinline__ void pdl_trigger() {
    asm volatile("griddepcontrol.launch_dependents;");
}
__device__ __forceinline__ void pdl_wait() {
    asm volatile("griddepcontrol.wait;" ::: "memory");
}

// ---------------- fp16 HMMA GEMM core: 128x256x64, 3-stage ------------------
#define BM 128
#define BN 256
#define BKE 64
#define SAS 72
#define SA_SZ (BM * SAS)
#define SB_SZ (BN * SAS)
#define STG_E (SA_SZ + SB_SZ)
#define SMEM_GEMM (3 * STG_E * 2)   // 165888 bytes

#define LDSM4(r0,r1,r2,r3,addr) \
  asm volatile("ldmatrix.sync.aligned.m8n8.x4.shared.b16 {%0,%1,%2,%3}, [%4];" \
   : "=r"(r0),"=r"(r1),"=r"(r2),"=r"(r3) : "r"(addr))

#define MMA16816(d, a, b) \
  asm volatile("mma.sync.aligned.m16n8k16.row.col.f32.f16.f16.f32 " \
    "{%0,%1,%2,%3}, {%4,%5,%6,%7}, {%8,%9}, {%0,%1,%2,%3};" \
    : "+f"(d[0]),"+f"(d[1]),"+f"(d[2]),"+f"(d[3]) \
    : "r"(a[0]),"r"(a[1]),"r"(a[2]),"r"(a[3]), "r"(b[0]),"r"(b[1]))

// W tiles (static weights) are prefetched BEFORE pdl_wait; A tiles after.
__device__ __forceinline__ void
gemm_main(const __half* __restrict__ A, int lda,
          const __half* __restrict__ W, int ldw,
          int m0, int n0, int K, float acw[4][8][4])
{
    extern __shared__ __align__(16) __half smem[];
    const int tid  = threadIdx.x;
    const int warp = tid >> 5;
    const int lane = tid & 31;
    const int wm = warp & 1;
    const int wn = warp >> 1;
    const int KT = K / BKE;

#pragma unroll
    for (int mi = 0; mi < 4; mi++)
#pragma unroll
        for (int ni = 0; ni < 8; ni++)
#pragma unroll
            for (int q = 0; q < 4; q++) acw[mi][ni][q] = 0.f;

    auto load_W = [&](int kt, int s) {
        const __half* Wp = W + kt * BKE;
        __half* sb0 = smem + s * STG_E + SA_SZ;
#pragma unroll
        for (int i = 0; i < 8; i++) {
            int idx = tid + i * 256;
            int row = idx >> 3;
            int ch  = idx & 7;
            unsigned sb = (unsigned)__cvta_generic_to_shared(&sb0[row * SAS + ch * 8]);
            const void* gw = Wp + (size_t)(n0 + row) * ldw + ch * 8;
            asm volatile("cp.async.cg.shared.global [%0], [%1], 16;" :: "r"(sb), "l"(gw));
        }
    };
    auto load_A = [&](int kt, int s) {
        const __half* Ap = A + kt * BKE;
        __half* sa0 = smem + s * STG_E;
#pragma unroll
        for (int i = 0; i < 4; i++) {
            int idx = tid + i * 256;
            int row = idx >> 3;
            int ch  = idx & 7;
            unsigned sa = (unsigned)__cvta_generic_to_shared(&sa0[row * SAS + ch * 8]);
            const void* ga = Ap + (size_t)(m0 + row) * lda + ch * 8;
            asm volatile("cp.async.cg.shared.global [%0], [%1], 16;" :: "r"(sa), "l"(ga));
        }
    };
    auto load_tiles = [&](int kt, int s) {
        load_A(kt, s);
        load_W(kt, s);
        asm volatile("cp.async.commit_group;");
    };

    // prologue: W tiles (independent of predecessor) first, then wait, then A
    load_W(0, 0);
    load_W(1, 1);
    pdl_wait();
    load_A(0, 0);
    asm volatile("cp.async.commit_group;");   // g0: W0, W1, A0
    load_A(1, 1);
    asm volatile("cp.async.commit_group;");   // g1: A1

    const int lt  = lane >> 3;
    const int lr  = lane & 7;

    int s = 0;
    for (int kt = 0; kt < KT; kt++) {
        asm volatile("cp.async.wait_group 1;");
        __syncthreads();

        const __half* pa = smem + s * STG_E;
        const __half* pb = pa + SA_SZ;
#pragma unroll
        for (int kq = 0; kq < 4; kq++) {
            const int k0 = kq * 16;
            unsigned af[4][4];
#pragma unroll
            for (int mi = 0; mi < 4; mi++) {
                int mrow = wm * 64 + mi * 16 + (lt & 1) * 8 + lr;
                int kcol = k0 + (lt >> 1) * 8;
                unsigned addr = (unsigned)__cvta_generic_to_shared(&pa[mrow * SAS + kcol]);
                LDSM4(af[mi][0], af[mi][1], af[mi][2], af[mi][3], addr);
            }
            unsigned bf[8][2];
#pragma unroll
            for (int nb = 0; nb < 4; nb++) {
                int nrow = wn * 64 + nb * 16 + (lt >> 1) * 8 + lr;
                int kcol = k0 + (lt & 1) * 8;
                unsigned addr = (unsigned)__cvta_generic_to_shared(&pb[nrow * SAS + kcol]);
                unsigned r0, r1, r2, r3;
                LDSM4(r0, r1, r2, r3, addr);
                bf[nb * 2][0] = r0;     bf[nb * 2][1] = r1;
                bf[nb * 2 + 1][0] = r2; bf[nb * 2 + 1][1] = r3;
            }
#pragma unroll
            for (int mi = 0; mi < 4; mi++)
#pragma unroll
                for (int ni = 0; ni < 8; ni++)
                    MMA16816(acw[mi][ni], af[mi], bf[ni]);
        }
        if (kt + 2 < KT) load_tiles(kt + 2, (s + 2 >= 3) ? s - 1 : s + 2);
        else asm volatile("cp.async.commit_group;");
        if (++s == 3) s = 0;
    }
}

// epilogue: fp32 accum + fp32 bias -> fp16 store (half2 pairs)
__device__ __forceinline__ void
gemm_epi_store(float acw[4][8][4], const float* __restrict__ bz,
               __half* __restrict__ C, int ldc, int m0, int n0)
{
    const int warp = threadIdx.x >> 5;
    const int lane = threadIdx.x & 31;
    const int wm = warp & 1;
    const int wn = warp >> 1;
#pragma unroll
    for (int mi = 0; mi < 4; mi++) {
        const int r0 = m0 + wm * 64 + mi * 16 + (lane >> 2);
#pragma unroll
        for (int ni = 0; ni < 8; ni++) {
            const int cc = n0 + wn * 64 + ni * 8 + (lane & 3) * 2;
            const float* a = acw[mi][ni];
            float b0 = bz[cc], b1 = bz[cc + 1];
            *(__half2*)&C[(size_t)r0 * ldc + cc] =
                __floats2half2_rn(a[0] + b0, a[1] + b1);
            *(__half2*)&C[(size_t)(r0 + 8) * ldc + cc] =
                __floats2half2_rn(a[2] + b0, a[3] + b1);
        }
    }
}

__global__ void __launch_bounds__(256, 1)
gemm256(const __half* __restrict__ A, int lda,
        const __half* __restrict__ W, int ldw,
        const float* __restrict__ bias,
        __half* __restrict__ C, int ldc, int K)
{
    pdl_trigger();
    float acw[4][8][4];
    gemm_main(A, lda, W, ldw, blockIdx.y * BM, blockIdx.x * BN, K, acw);
    gemm_epi_store(acw, bias, C, ldc, blockIdx.y * BM, blockIdx.x * BN);
}

// Combined AG + U + G2 launch: grid (10, 32, 2).
//   z=0, x<9 : AG tile.  z=1, x<9 : U tile (l=x/3, nt=x%3).  z=1, x==9 : G2.
__global__ void __launch_bounds__(256, 1)
gemm_agu(const __half* __restrict__ hsp,
         const __half* __restrict__ Whc, const float* __restrict__ bhc,
         __half* __restrict__ AG,
         const __half* __restrict__ Whfio, const float* __restrict__ bhfio,
         __half* __restrict__ U,
         const float* __restrict__ hf, const float* __restrict__ whg,
         const float* __restrict__ bhg, float* __restrict__ G2)
{
    pdl_trigger();
    if (blockIdx.z == 0) {
        if (blockIdx.x >= 9) { pdl_wait(); return; }
        float acw[4][8][4];
        gemm_main(hsp, SH, Whc, SH, blockIdx.y * BM, blockIdx.x * BN, SH, acw);
        gemm_epi_store(acw, bhc, AG, NAG, blockIdx.y * BM, blockIdx.x * BN);
    } else if (blockIdx.x < 9) {
        const int l  = blockIdx.x / 3;
        const int xt = blockIdx.x - l * 3;
        float acw[4][8][4];
        gemm_main(hsp + l * Hh, SH, Whfio + (size_t)l * NU * Hh, Hh,
                  blockIdx.y * BM, xt * BN, Hh, acw);
        gemm_epi_store(acw, bhfio + l * NU, U + (size_t)l * Bsz * NU, NU,
                       blockIdx.y * BM, xt * BN);
    } else {
        // G2: 9 dots of 768 per row (reads h_cat(t-1)), 128 rows per m-tile
        pdl_wait();
        const int m0 = blockIdx.y * BM;
        const int warp = threadIdx.x >> 5;
        const int lane = threadIdx.x & 31;
        for (int rr = 0; rr < 16; rr++) {
            int row = m0 + warp * 16 + rr;
            const float* hr = hf + (size_t)row * SH;
            float p[9];
#pragma unroll
            for (int o = 0; o < 9; o++) p[o] = 0.f;
            for (int i = 0; i < 24; i++) {
                int k = lane + 32 * i;
                float hv = hr[k];
#pragma unroll
                for (int o = 0; o < 9; o++) p[o] += hv * whg[o * SH + k];
            }
#pragma unroll
            for (int o = 0; o < 9; o++) {
#pragma unroll
                for (int off = 16; off; off >>= 1)
                    p[o] += __shfl_xor_sync(0xFFFFFFFFu, p[o], off);
            }
            if (lane == 0) {
#pragma unroll
                for (int o = 0; o < 9; o++)
                    G2[(size_t)row * 12 + o] = p[o] + bhg[o];
            }
        }
    }
}

// ---------------- per-layer LSTM cell (block = one batch row) ---------------
__global__ void __launch_bounds__(256)
cell_kernel(const __half* __restrict__ Z, const __half* __restrict__ U,
            const __half* __restrict__ AG, const float* __restrict__ G2,
            const float* __restrict__ G0,
            const float* __restrict__ wig3, const float* __restrict__ big3,
            const float* __restrict__ hin,
            __half* __restrict__ hsp, float* __restrict__ hf,
            float* __restrict__ c, float* __restrict__ featf, int l, int t)
{
    pdl_trigger();
    pdl_wait();
    const int b = blockIdx.x;
    const int j = threadIdx.x;
    const int warp = j >> 5;
    const int lane = j & 31;
    __shared__ float red[3][8];

    float gin0, gin1, gin2;
    if (l == 0) {
        gin0 = G0[(size_t)b * 3 + 0];
        gin1 = G0[(size_t)b * 3 + 1];
        gin2 = G0[(size_t)b * 3 + 2];
    } else {
        float iv = hin[(size_t)b * SH + j];
        float p0 = iv * wig3[j];
        float p1 = iv * wig3[256 + j];
        float p2 = iv * wig3[512 + j];
#pragma unroll
        for (int off = 16; off; off >>= 1) {
            p0 += __shfl_xor_sync(0xFFFFFFFFu, p0, off);
            p1 += __shfl_xor_sync(0xFFFFFFFFu, p1, off);
            p2 += __shfl_xor_sync(0xFFFFFFFFu, p2, off);
        }
        if (lane == 0) { red[0][warp] = p0; red[1][warp] = p1; red[2][warp] = p2; }
        __syncthreads();
        float s0 = 0.f, s1 = 0.f, s2 = 0.f;
#pragma unroll
        for (int w = 0; w < 8; w++) { s0 += red[0][w]; s1 += red[1][w]; s2 += red[2][w]; }
        gin0 = s0 + big3[0];
        gin1 = s1 + big3[1];
        gin2 = s2 + big3[2];
    }

    const float* g2p = G2 + (size_t)b * 12 + l * 3;
    float g0 = sigf(gin0 + g2p[0]);
    float g1 = sigf(gin1 + g2p[1]);
    float g2v = sigf(gin2 + g2p[2]);

    const __half* Zb = Z + (size_t)b * NZS;
    const __half* Ub = U + (size_t)b * NU;
    const __half* Gb = AG + (size_t)b * NAG + l * SH;
    float aux = g0 * __half2float(Gb[j]) + g1 * __half2float(Gb[256 + j])
              + g2v * __half2float(Gb[512 + j]);

    float fg = sigf(__half2float(Zb[j])       + __half2float(Ub[j]));
    float ig = sigf(__half2float(Zb[256 + j]) + __half2float(Ub[256 + j]));
    float og = sigf(__half2float(Zb[512 + j]) + __half2float(Ub[512 + j]));
    float ct = tanhf(__half2float(Zb[768 + j]) + aux);

    size_t sidx = (size_t)b * SH + l * Hh + j;
    float cn = fg * c[sidx] + ig * ct;
    float hn = og * cn;
    c[sidx] = cn;
    hf[sidx] = hn;
    hsp[sidx] = __float2half(hn);
    if (featf) featf[(size_t)b * FEATK + t * Hh + j] = hn;
}

// ---------------- small fp32 dot kernels ------------------------------------
__global__ void glog0_kernel(const float* __restrict__ x,
                             const float* __restrict__ wig,
                             const float* __restrict__ big,
                             float* __restrict__ G0)
{
    int gw = (blockIdx.x * blockDim.x + threadIdx.x) >> 5;
    int lane = threadIdx.x & 31;
    if (gw >= Bsz * 3) return;
    int b = gw / 3;
    int r = gw - b * 3;
    const float* xr = x + (size_t)b * Dd;
    const float* wr = wig + (size_t)r * Dd;
    float sum = 0.f;
#pragma unroll 4
    for (int k = lane; k < Dd; k += 32) sum += xr[k] * wr[k];
#pragma unroll
    for (int off = 16; off; off >>= 1) sum += __shfl_xor_sync(0xFFFFFFFFu, sum, off);
    if (lane == 0) G0[(size_t)b * 3 + r] = sum + big[r];
}

__global__ void out_kernel(const float* __restrict__ featf,
                           const float* __restrict__ wl,
                           const float* __restrict__ bl,
                           float* __restrict__ out)
{
    pdl_trigger();
    pdl_wait();
    int gw = (blockIdx.x * blockDim.x + threadIdx.x) >> 5;
    int lane = threadIdx.x & 31;
    if (gw >= Bsz * OUTN) return;
    int b = gw / OUTN;
    int o = gw - b * OUTN;
    const float* fr = featf + (size_t)b * FEATK;
    const float* wr = wl + (size_t)o * FEATK;
    float sum = 0.f;
#pragma unroll 8
    for (int k = lane; k < FEATK; k += 32) sum += fr[k] * wr[k];
#pragma unroll
    for (int off = 16; off; off >>= 1) sum += __shfl_xor_sync(0xFFFFFFFFu, sum, off);
    if (lane == 0) out[(size_t)b * OUTN + o] = sigf(sum + bl[o]);
}

// ---------------- state init / splits --------------------------------------
__global__ void init_state(const float* __restrict__ hid, const float* __restrict__ cur,
                           __half* __restrict__ hsp, float* __restrict__ hf,
                           float* __restrict__ c)
{
    int i = blockIdx.x * blockDim.x + threadIdx.x;
    const int total = Ss * Bsz * Hh;
    if (i >= total) return;
    int l = i / (Bsz * Hh);
    int r = i - l * (Bsz * Hh);
    int b = r >> 8;
    int j = r & 255;
    float v = hid[i];
    size_t dst = (size_t)b * SH + l * Hh + j;
    hsp[dst] = __float2half(v);
    hf[dst]  = v;
    c[dst]   = cur[i];
}

__global__ void conv_x(const float* __restrict__ x, __half* __restrict__ xsp)
{
    int i = blockIdx.x * blockDim.x + threadIdx.x;
    if (i >= Bsz * Dd) return;
    xsp[i] = __float2half(x[i]);
}

// ---------------- fused weight repack (fp32 -> fp16, concat rows) ----------
#define RW1 (Ss * NZS * Dd)
#define RW2 (RW1 + Ss * NU * Hh)
#define RW3 (RW2 + NAG * SH)
#define RW4 (RW3 + Ss * NZS)
#define RW5 (RW4 + Ss * NU)

__global__ void repack_all(const float* __restrict__ wif, const float* __restrict__ wii,
                           const float* __restrict__ wio, const float* __restrict__ wic,
                           const float* __restrict__ whf, const float* __restrict__ whi,
                           const float* __restrict__ who, const float* __restrict__ whc,
                           const float* __restrict__ bif, const float* __restrict__ bii,
                           const float* __restrict__ bio, const float* __restrict__ bic,
                           const float* __restrict__ bhf, const float* __restrict__ bhi,
                           const float* __restrict__ bho,
                           __half* __restrict__ WiAll, __half* __restrict__ Whfio,
                           __half* __restrict__ Whc,
                           float* __restrict__ biAll, float* __restrict__ bhfio)
{
    int idx = blockIdx.x * blockDim.x + threadIdx.x;
    if (idx < RW1) {
        int k = idx % Dd;
        int r = (idx / Dd) % NZS;
        int l = idx / (Dd * NZS);
        float v;
        if      (r < 256) v = wif[((size_t)l * Hh + r)       * Dd + k];
        else if (r < 512) v = wii[((size_t)l * Hh + r - 256) * Dd + k];
        else if (r < 768) v = wio[((size_t)l * Hh + r - 512) * Dd + k];
        else              v = wic[((size_t)l * Hh + r - 768) * Dd + k];
        WiAll[idx] = __float2half(v);
    } else if (idx < RW2) {
        int t = idx - RW1;
        int k = t % Hh;
        int r = (t / Hh) % NU;
        int l = t / (Hh * NU);
        float v;
        if      (r < 256) v = whf[((size_t)l * Hh + r)       * Hh + k];
        else if (r < 512) v = whi[((size_t)l * Hh + r - 256) * Hh + k];
        else              v = who[((size_t)l * Hh + r - 512) * Hh + k];
        Whfio[t] = __float2half(v);
    } else if (idx < RW3) {
        int t = idx - RW2;
        Whc[t] = __float2half(whc[t]);
    } else if (idx < RW4) {
        int t = idx - RW3;
        int r = t % NZS, l = t / NZS;
        float v;
        if      (r < 256) v = bif[l * Hh + r];
        else if (r < 512) v = bii[l * Hh + r - 256];
        else if (r < 768) v = bio[l * Hh + r - 512];
        else              v = bic[l * Hh + r - 768];
        biAll[t] = v;
    } else if (idx < RW5) {
        int t = idx - RW4;
        int r = t % NU, l = t / NU;
        float v;
        if      (r < 256) v = bhf[l * Hh + r];
        else if (r < 512) v = bhi[l * Hh + r - 256];
        else              v = bho[l * Hh + r - 512];
        bhfio[t] = v;
    }
}

// ---------------- orchestration --------------------------------------------
extern "C" void kernel_launch(void* const* d_in, const int* in_sizes, int n_in,
                              void* d_out, int out_size)
{
    (void)in_sizes; (void)n_in; (void)out_size;
    const float* x    = (const float*)d_in[0];
    const float* hid0 = (const float*)d_in[1];
    const float* cur0 = (const float*)d_in[2];
    const float* Wi_f = (const float*)d_in[3];
    const float* bi_f = (const float*)d_in[4];
    const float* Wi_i = (const float*)d_in[5];
    const float* bi_i = (const float*)d_in[6];
    const float* Wi_o = (const float*)d_in[7];
    const float* bi_o = (const float*)d_in[8];
    const float* Wi_c = (const float*)d_in[9];
    const float* bi_c = (const float*)d_in[10];
    const float* Wi_g = (const float*)d_in[11];
    const float* bi_g = (const float*)d_in[12];
    const float* Wh_f = (const float*)d_in[13];
    const float* bh_f = (const float*)d_in[14];
    const float* Wh_i = (const float*)d_in[15];
    const float* bh_i = (const float*)d_in[16];
    const float* Wh_o = (const float*)d_in[17];
    const float* bh_o = (const float*)d_in[18];
    const float* Wh_g = (const float*)d_in[19];
    const float* bh_g = (const float*)d_in[20];
    const float* Wh_c = (const float*)d_in[21];
    const float* bh_c = (const float*)d_in[22];
    const float* W_last = (const float*)d_in[23];
    const float* b_last = (const float*)d_in[24];
    float* out = (float*)d_out;

    __half *hsp, *xsp, *WiAll, *Whfio, *Whc, *U, *AG, *Z, *Z0;
    float *hf, *cst, *G2, *G0, *featf, *biAll, *bhfio;
    cudaGetSymbolAddress((void**)&hsp,   g_hsp);
    cudaGetSymbolAddress((void**)&hf,    g_hf);
    cudaGetSymbolAddress((void**)&xsp,   g_xsp);
    cudaGetSymbolAddress((void**)&cst,   g_c);
    cudaGetSymbolAddress((void**)&U,     g_U);
    cudaGetSymbolAddress((void**)&AG,    g_AG);
    cudaGetSymbolAddress((void**)&G2,    g_G2);
    cudaGetSymbolAddress((void**)&G0,    g_G0);
    cudaGetSymbolAddress((void**)&Z,     g_Z);
    cudaGetSymbolAddress((void**)&Z0,    g_Z0);
    cudaGetSymbolAddress((void**)&featf, g_featf);
    cudaGetSymbolAddress((void**)&WiAll, g_WiAll);
    cudaGetSymbolAddress((void**)&biAll, g_biAll);
    cudaGetSymbolAddress((void**)&Whfio, g_Whfio);
    cudaGetSymbolAddress((void**)&bhfio, g_bhfio);
    cudaGetSymbolAddress((void**)&Whc,   g_Whc);

    cudaFuncSetAttribute(gemm256,  cudaFuncAttributeMaxDynamicSharedMemorySize, SMEM_GEMM);
    cudaFuncSetAttribute(gemm_agu, cudaFuncAttributeMaxDynamicSharedMemorySize, SMEM_GEMM);

    const dim3 blk(256);

    // PDL launch attribute (applies to loop kernels)
    cudaLaunchAttribute pat[1];
    pat[0].id = cudaLaunchAttributeProgrammaticStreamSerialization;
    pat[0].val.programmaticStreamSerializationAllowed = 1;
    auto mkcfg = [&](dim3 g, size_t sm) {
        cudaLaunchConfig_t cf;
        cf.gridDim = g;
        cf.blockDim = blk;
        cf.dynamicSmemBytes = sm;
        cf.stream = 0;
        cf.attrs = pat;
        cf.numAttrs = 1;
        return cf;
    };

    // ---- setup (regular launches) ----
    init_state<<<(Ss * Bsz * Hh + 255) / 256, blk>>>(hid0, cur0, hsp, hf, cst);
    conv_x<<<(Bsz * Dd + 255) / 256, blk>>>(x, xsp);
    repack_all<<<(RW5 + 255) / 256, blk>>>(Wi_f, Wi_i, Wi_o, Wi_c,
                                           Wh_f, Wh_i, Wh_o, Wh_c,
                                           bi_f, bi_i, bi_o, bi_c,
                                           bh_f, bh_i, bh_o,
                                           WiAll, Whfio, Whc, biAll, bhfio);
    glog0_kernel<<<(Bsz * 3 * 32 + 255) / 256, blk>>>(x, Wi_g, bi_g, G0);
    // Z0 = x @ Wi[0]^T + bias  (time-invariant)
    gemm256<<<dim3(4, 32, 1), blk, SMEM_GEMM>>>(xsp, Dd, WiAll, Dd,
                                                biAll, Z0, NZS, Dd);

    for (int t = 0; t < REPT; t++) {
        // AG + U + G2 (all read state(t-1))
        {
            cudaLaunchConfig_t cf = mkcfg(dim3(10, 32, 2), SMEM_GEMM);
            cudaLaunchKernelEx(&cf, gemm_agu,
                (const __half*)hsp, (const __half*)Whc, bh_c, AG,
                (const __half*)Whfio, (const float*)bhfio, U,
                (const float*)hf, Wh_g, bh_g, G2);
        }
        // cell0
        {
            cudaLaunchConfig_t cf = mkcfg(dim3(Bsz), 0);
            cudaLaunchKernelEx(&cf, cell_kernel,
                (const __half*)Z0, (const __half*)U, (const __half*)AG,
                (const float*)G2, (const float*)G0,
                (const float*)nullptr, (const float*)nullptr, (const float*)nullptr,
                hsp, hf, cst, (float*)nullptr, 0, t);
        }
        // Z1
        {
            cudaLaunchConfig_t cf = mkcfg(dim3(4, 32, 1), SMEM_GEMM);
            cudaLaunchKernelEx(&cf, gemm256,
                (const __half*)hsp, (int)SH,
                (const __half*)(WiAll + (size_t)NZS * Dd), (int)Dd,
                (const float*)(biAll + NZS), Z, (int)NZS, (int)Hh);
        }
        // cell1
        {
            cudaLaunchConfig_t cf = mkcfg(dim3(Bsz), 0);
            cudaLaunchKernelEx(&cf, cell_kernel,
                (const __half*)Z, (const __half*)(U + (size_t)Bsz * NU),
                (const __half*)AG, (const float*)G2, (const float*)nullptr,
                (const float*)(Wi_g + (size_t)3 * Dd), (const float*)(bi_g + 3),
                (const float*)hf,
                hsp, hf, cst, (float*)nullptr, 1, t);
        }
        // Z2
        {
            cudaLaunchConfig_t cf = mkcfg(dim3(4, 32, 1), SMEM_GEMM);
            cudaLaunchKernelEx(&cf, gemm256,
                (const __half*)(hsp + Hh), (int)SH,
                (const __half*)(WiAll + (size_t)2 * NZS * Dd), (int)Dd,
                (const float*)(biAll + 2 * NZS), Z, (int)NZS, (int)Hh);
        }
        // cell2
        {
            float* fptr = (t < REPT - 1) ? featf : nullptr;
            cudaLaunchConfig_t cf = mkcfg(dim3(Bsz), 0);
            cudaLaunchKernelEx(&cf, cell_kernel,
                (const __half*)Z, (const __half*)(U + (size_t)2 * Bsz * NU),
                (const __half*)AG, (const float*)G2, (const float*)nullptr,
                (const float*)(Wi_g + (size_t)6 * Dd), (const float*)(bi_g + 6),
                (const float*)(hf + Hh),
                hsp, hf, cst, fptr, 2, t);
        }
    }

    {
        cudaLaunchConfig_t cf = mkcfg(dim3((Bsz * OUTN * 32 + 255) / 256), 0);
        cudaLaunchKernelEx(&cf, out_kernel, (const float*)featf, W_last, b_last, out);
    }
}

// round 15
// speedup vs baseline: 1.2191x; 1.0505x over previous
#include <cuda_runtime.h>
#include <cuda_fp16.h>
#include <math.h>
#include <stdint.h>

// Problem constants
#define Bsz  4096
#define Dd   256
#define Hh   256
#define Ss   3
#define REPT 10
#define OUTN 44
#define SH   768      // S*H
#define NZS  1024     // Z rows: f,i,o,c blocks of 256
#define NU   768
#define NAG  2304     // fused AG: 3 layers x 768 aux rows
#define FEATK 2304    // (REP-1)*H
#define NLP  256      // padded W_last rows

// ---------------- scratch (static device arrays; no cudaMalloc) ------------
__device__ __half g_hsp[(size_t)Bsz * SH];        // fp16 hidden state (h_cat layout)
__device__ float  g_hf[(size_t)Bsz * SH];         // fp32 h_cat copy
__device__ __half g_xsp[(size_t)Bsz * Dd];        // fp16 x
__device__ float  g_c[(size_t)Bsz * SH];
__device__ __half g_U[(size_t)Ss * Bsz * NU];     // fp16 preacts
__device__ __half g_AG[(size_t)Bsz * NAG];        // fp16 preacts
__device__ float  g_G2[(size_t)Bsz * 12];         // Wh_g . h_cat + bh_g (9 used)
__device__ float  g_G0[(size_t)Bsz * 3];          // Wi_g[0] . x + bi_g[0]
__device__ __half g_Z[(size_t)Bsz * NZS];         // fp16 preacts
__device__ __half g_Z0[(size_t)Bsz * NZS];
__device__ __half g_featf[(size_t)Bsz * FEATK];   // fp16 features
__device__ __half g_WiAll[(size_t)Ss * NZS * Dd];
__device__ float  g_biAll[Ss * NZS];
__device__ __half g_Whfio[(size_t)Ss * NU * Hh];
__device__ float  g_bhfio[Ss * NU];
__device__ __half g_Whc[(size_t)NAG * SH];
__device__ __half g_Wlast[(size_t)NLP * FEATK];   // padded, rows >=44 zero

__device__ __forceinline__ float sigf(float x) { return 1.0f / (1.0f + expf(-x)); }

// ---------------- PDL intrinsics --------------------------------------------
__device__ __forceinline__ void pdl_trigger() {
    asm volatile("griddepcontrol.launch_dependents;");
}
__device__ __forceinline__ void pdl_wait() {
    asm volatile("griddepcontrol.wait;" ::: "memory");
}

// ---------------- fp16 HMMA GEMM core: 128x256x64, 3-stage ------------------
#define BM 128
#define BN 256
#define BKE 64
#define SAS 72
#define SA_SZ (BM * SAS)
#define SB_SZ (BN * SAS)
#define STG_E (SA_SZ + SB_SZ)
#define SMEM_GEMM (3 * STG_E * 2)   // 165888 bytes

#define LDSM4(r0,r1,r2,r3,addr) \
  asm volatile("ldmatrix.sync.aligned.m8n8.x4.shared.b16 {%0,%1,%2,%3}, [%4];" \
   : "=r"(r0),"=r"(r1),"=r"(r2),"=r"(r3) : "r"(addr))

#define MMA16816(d, a, b) \
  asm volatile("mma.sync.aligned.m16n8k16.row.col.f32.f16.f16.f32 " \
    "{%0,%1,%2,%3}, {%4,%5,%6,%7}, {%8,%9}, {%0,%1,%2,%3};" \
    : "+f"(d[0]),"+f"(d[1]),"+f"(d[2]),"+f"(d[3]) \
    : "r"(a[0]),"r"(a[1]),"r"(a[2]),"r"(a[3]), "r"(b[0]),"r"(b[1]))

// W tiles (static weights) are prefetched BEFORE pdl_wait; A tiles after.
__device__ __forceinline__ void
gemm_main(const __half* __restrict__ A, int lda,
          const __half* __restrict__ W, int ldw,
          int m0, int n0, int K, float acw[4][8][4])
{
    extern __shared__ __align__(16) __half smem[];
    const int tid  = threadIdx.x;
    const int warp = tid >> 5;
    const int lane = tid & 31;
    const int wm = warp & 1;
    const int wn = warp >> 1;
    const int KT = K / BKE;

#pragma unroll
    for (int mi = 0; mi < 4; mi++)
#pragma unroll
        for (int ni = 0; ni < 8; ni++)
#pragma unroll
            for (int q = 0; q < 4; q++) acw[mi][ni][q] = 0.f;

    auto load_W = [&](int kt, int s) {
        const __half* Wp = W + kt * BKE;
        __half* sb0 = smem + s * STG_E + SA_SZ;
#pragma unroll
        for (int i = 0; i < 8; i++) {
            int idx = tid + i * 256;
            int row = idx >> 3;
            int ch  = idx & 7;
            unsigned sb = (unsigned)__cvta_generic_to_shared(&sb0[row * SAS + ch * 8]);
            const void* gw = Wp + (size_t)(n0 + row) * ldw + ch * 8;
            asm volatile("cp.async.cg.shared.global [%0], [%1], 16;" :: "r"(sb), "l"(gw));
        }
    };
    auto load_A = [&](int kt, int s) {
        const __half* Ap = A + kt * BKE;
        __half* sa0 = smem + s * STG_E;
#pragma unroll
        for (int i = 0; i < 4; i++) {
            int idx = tid + i * 256;
            int row = idx >> 3;
            int ch  = idx & 7;
            unsigned sa = (unsigned)__cvta_generic_to_shared(&sa0[row * SAS + ch * 8]);
            const void* ga = Ap + (size_t)(m0 + row) * lda + ch * 8;
            asm volatile("cp.async.cg.shared.global [%0], [%1], 16;" :: "r"(sa), "l"(ga));
        }
    };
    auto load_tiles = [&](int kt, int s) {
        load_A(kt, s);
        load_W(kt, s);
        asm volatile("cp.async.commit_group;");
    };

    // prologue: W tiles (independent of predecessor) first, then wait, then A
    load_W(0, 0);
    load_W(1, 1);
    pdl_wait();
    load_A(0, 0);
    asm volatile("cp.async.commit_group;");   // g0: W0, W1, A0
    load_A(1, 1);
    asm volatile("cp.async.commit_group;");   // g1: A1

    const int lt  = lane >> 3;
    const int lr  = lane & 7;

    int s = 0;
    for (int kt = 0; kt < KT; kt++) {
        asm volatile("cp.async.wait_group 1;");
        __syncthreads();

        const __half* pa = smem + s * STG_E;
        const __half* pb = pa + SA_SZ;
#pragma unroll
        for (int kq = 0; kq < 4; kq++) {
            const int k0 = kq * 16;
            unsigned af[4][4];
#pragma unroll
            for (int mi = 0; mi < 4; mi++) {
                int mrow = wm * 64 + mi * 16 + (lt & 1) * 8 + lr;
                int kcol = k0 + (lt >> 1) * 8;
                unsigned addr = (unsigned)__cvta_generic_to_shared(&pa[mrow * SAS + kcol]);
                LDSM4(af[mi][0], af[mi][1], af[mi][2], af[mi][3], addr);
            }
            unsigned bf[8][2];
#pragma unroll
            for (int nb = 0; nb < 4; nb++) {
                int nrow = wn * 64 + nb * 16 + (lt >> 1) * 8 + lr;
                int kcol = k0 + (lt & 1) * 8;
                unsigned addr = (unsigned)__cvta_generic_to_shared(&pb[nrow * SAS + kcol]);
                unsigned r0, r1, r2, r3;
                LDSM4(r0, r1, r2, r3, addr);
                bf[nb * 2][0] = r0;     bf[nb * 2][1] = r1;
                bf[nb * 2 + 1][0] = r2; bf[nb * 2 + 1][1] = r3;
            }
#pragma unroll
            for (int mi = 0; mi < 4; mi++)
#pragma unroll
                for (int ni = 0; ni < 8; ni++)
                    MMA16816(acw[mi][ni], af[mi], bf[ni]);
        }
        if (kt + 2 < KT) load_tiles(kt + 2, (s + 2 >= 3) ? s - 1 : s + 2);
        else asm volatile("cp.async.commit_group;");
        if (++s == 3) s = 0;
    }
}

// epilogue: fp32 accum + fp32 bias -> fp16 store (half2 pairs)
__device__ __forceinline__ void
gemm_epi_store(float acw[4][8][4], const float* __restrict__ bz,
               __half* __restrict__ C, int ldc, int m0, int n0)
{
    const int warp = threadIdx.x >> 5;
    const int lane = threadIdx.x & 31;
    const int wm = warp & 1;
    const int wn = warp >> 1;
#pragma unroll
    for (int mi = 0; mi < 4; mi++) {
        const int r0 = m0 + wm * 64 + mi * 16 + (lane >> 2);
#pragma unroll
        for (int ni = 0; ni < 8; ni++) {
            const int cc = n0 + wn * 64 + ni * 8 + (lane & 3) * 2;
            const float* a = acw[mi][ni];
            float b0 = bz[cc], b1 = bz[cc + 1];
            *(__half2*)&C[(size_t)r0 * ldc + cc] =
                __floats2half2_rn(a[0] + b0, a[1] + b1);
            *(__half2*)&C[(size_t)(r0 + 8) * ldc + cc] =
                __floats2half2_rn(a[2] + b0, a[3] + b1);
        }
    }
}

__global__ void __launch_bounds__(256, 1)
gemm256(const __half* __restrict__ A, int lda,
        const __half* __restrict__ W, int ldw,
        const float* __restrict__ bias,
        __half* __restrict__ C, int ldc, int K)
{
    pdl_trigger();
    float acw[4][8][4];
    gemm_main(A, lda, W, ldw, blockIdx.y * BM, blockIdx.x * BN, K, acw);
    gemm_epi_store(acw, bias, C, ldc, blockIdx.y * BM, blockIdx.x * BN);
}

// Final projection: out = sigmoid(feat @ W_last^T + b_last), N padded to 256.
__global__ void __launch_bounds__(256, 1)
gemm_out(const __half* __restrict__ feat,
         const __half* __restrict__ Wl, const float* __restrict__ bl,
         float* __restrict__ out)
{
    pdl_trigger();
    float acw[4][8][4];
    const int m0 = blockIdx.y * BM;
    gemm_main(feat, FEATK, Wl, FEATK, m0, 0, FEATK, acw);

    const int warp = threadIdx.x >> 5;
    const int lane = threadIdx.x & 31;
    const int wm = warp & 1;
    const int wn = warp >> 1;
#pragma unroll
    for (int mi = 0; mi < 4; mi++) {
        const int r0 = m0 + wm * 64 + mi * 16 + (lane >> 2);
#pragma unroll
        for (int ni = 0; ni < 8; ni++) {
            const int cc = wn * 64 + ni * 8 + (lane & 3) * 2;
            if (cc >= OUTN) continue;
            const float* a = acw[mi][ni];
            out[(size_t)r0 * OUTN + cc] = sigf(a[0] + bl[cc]);
            out[(size_t)(r0 + 8) * OUTN + cc] = sigf(a[2] + bl[cc]);
            if (cc + 1 < OUTN) {
                out[(size_t)r0 * OUTN + cc + 1] = sigf(a[1] + bl[cc + 1]);
                out[(size_t)(r0 + 8) * OUTN + cc + 1] = sigf(a[3] + bl[cc + 1]);
            }
        }
    }
}

// Combined AG + U + G2 launch: grid (10, 32, 2).
//   z=0, x<9 : AG tile.  z=1, x<9 : U tile (l=x/3, nt=x%3).  z=1, x==9 : G2.
__global__ void __launch_bounds__(256, 1)
gemm_agu(const __half* __restrict__ hsp,
         const __half* __restrict__ Whc, const float* __restrict__ bhc,
         __half* __restrict__ AG,
         const __half* __restrict__ Whfio, const float* __restrict__ bhfio,
         __half* __restrict__ U,
         const float* __restrict__ hf, const float* __restrict__ whg,
         const float* __restrict__ bhg, float* __restrict__ G2)
{
    pdl_trigger();
    if (blockIdx.z == 0) {
        if (blockIdx.x >= 9) { pdl_wait(); return; }
        float acw[4][8][4];
        gemm_main(hsp, SH, Whc, SH, blockIdx.y * BM, blockIdx.x * BN, SH, acw);
        gemm_epi_store(acw, bhc, AG, NAG, blockIdx.y * BM, blockIdx.x * BN);
    } else if (blockIdx.x < 9) {
        const int l  = blockIdx.x / 3;
        const int xt = blockIdx.x - l * 3;
        float acw[4][8][4];
        gemm_main(hsp + l * Hh, SH, Whfio + (size_t)l * NU * Hh, Hh,
                  blockIdx.y * BM, xt * BN, Hh, acw);
        gemm_epi_store(acw, bhfio + l * NU, U + (size_t)l * Bsz * NU, NU,
                       blockIdx.y * BM, xt * BN);
    } else {
        // G2: 9 dots of 768 per row (reads h_cat(t-1)), 128 rows per m-tile
        pdl_wait();
        const int m0 = blockIdx.y * BM;
        const int warp = threadIdx.x >> 5;
        const int lane = threadIdx.x & 31;
        for (int rr = 0; rr < 16; rr++) {
            int row = m0 + warp * 16 + rr;
            const float* hr = hf + (size_t)row * SH;
            float p[9];
#pragma unroll
            for (int o = 0; o < 9; o++) p[o] = 0.f;
            for (int i = 0; i < 24; i++) {
                int k = lane + 32 * i;
                float hv = hr[k];
#pragma unroll
                for (int o = 0; o < 9; o++) p[o] += hv * whg[o * SH + k];
            }
#pragma unroll
            for (int o = 0; o < 9; o++) {
#pragma unroll
                for (int off = 16; off; off >>= 1)
                    p[o] += __shfl_xor_sync(0xFFFFFFFFu, p[o], off);
            }
            if (lane == 0) {
#pragma unroll
                for (int o = 0; o < 9; o++)
                    G2[(size_t)row * 12 + o] = p[o] + bhg[o];
            }
        }
    }
}

// ---------------- per-layer LSTM cell (block = one batch row) ---------------
__global__ void __launch_bounds__(256)
cell_kernel(const __half* __restrict__ Z, const __half* __restrict__ U,
            const __half* __restrict__ AG, const float* __restrict__ G2,
            const float* __restrict__ G0,
            const float* __restrict__ wig3, const float* __restrict__ big3,
            const float* __restrict__ hin,
            __half* __restrict__ hsp, float* __restrict__ hf,
            float* __restrict__ c, __half* __restrict__ featf, int l, int t)
{
    pdl_trigger();
    pdl_wait();
    const int b = blockIdx.x;
    const int j = threadIdx.x;
    const int warp = j >> 5;
    const int lane = j & 31;
    __shared__ float red[3][8];

    float gin0, gin1, gin2;
    if (l == 0) {
        gin0 = G0[(size_t)b * 3 + 0];
        gin1 = G0[(size_t)b * 3 + 1];
        gin2 = G0[(size_t)b * 3 + 2];
    } else {
        float iv = hin[(size_t)b * SH + j];
        float p0 = iv * wig3[j];
        float p1 = iv * wig3[256 + j];
        float p2 = iv * wig3[512 + j];
#pragma unroll
        for (int off = 16; off; off >>= 1) {
            p0 += __shfl_xor_sync(0xFFFFFFFFu, p0, off);
            p1 += __shfl_xor_sync(0xFFFFFFFFu, p1, off);
            p2 += __shfl_xor_sync(0xFFFFFFFFu, p2, off);
        }
        if (lane == 0) { red[0][warp] = p0; red[1][warp] = p1; red[2][warp] = p2; }
        __syncthreads();
        float s0 = 0.f, s1 = 0.f, s2 = 0.f;
#pragma unroll
        for (int w = 0; w < 8; w++) { s0 += red[0][w]; s1 += red[1][w]; s2 += red[2][w]; }
        gin0 = s0 + big3[0];
        gin1 = s1 + big3[1];
        gin2 = s2 + big3[2];
    }

    const float* g2p = G2 + (size_t)b * 12 + l * 3;
    float g0 = sigf(gin0 + g2p[0]);
    float g1 = sigf(gin1 + g2p[1]);
    float g2v = sigf(gin2 + g2p[2]);

    const __half* Zb = Z + (size_t)b * NZS;
    const __half* Ub = U + (size_t)b * NU;
    const __half* Gb = AG + (size_t)b * NAG + l * SH;
    float aux = g0 * __half2float(Gb[j]) + g1 * __half2float(Gb[256 + j])
              + g2v * __half2float(Gb[512 + j]);

    float fg = sigf(__half2float(Zb[j])       + __half2float(Ub[j]));
    float ig = sigf(__half2float(Zb[256 + j]) + __half2float(Ub[256 + j]));
    float og = sigf(__half2float(Zb[512 + j]) + __half2float(Ub[512 + j]));
    float ct = tanhf(__half2float(Zb[768 + j]) + aux);

    size_t sidx = (size_t)b * SH + l * Hh + j;
    float cn = fg * c[sidx] + ig * ct;
    float hn = og * cn;
    c[sidx] = cn;
    hf[sidx] = hn;
    __half hh = __float2half(hn);
    hsp[sidx] = hh;
    if (featf) featf[(size_t)b * FEATK + t * Hh + j] = hh;
}

// ---------------- small fp32 dot kernels ------------------------------------
__global__ void glog0_kernel(const float* __restrict__ x,
                             const float* __restrict__ wig,
                             const float* __restrict__ big,
                             float* __restrict__ G0)
{
    int gw = (blockIdx.x * blockDim.x + threadIdx.x) >> 5;
    int lane = threadIdx.x & 31;
    if (gw >= Bsz * 3) return;
    int b = gw / 3;
    int r = gw - b * 3;
    const float* xr = x + (size_t)b * Dd;
    const float* wr = wig + (size_t)r * Dd;
    float sum = 0.f;
#pragma unroll 4
    for (int k = lane; k < Dd; k += 32) sum += xr[k] * wr[k];
#pragma unroll
    for (int off = 16; off; off >>= 1) sum += __shfl_xor_sync(0xFFFFFFFFu, sum, off);
    if (lane == 0) G0[(size_t)b * 3 + r] = sum + big[r];
}

// ---------------- state init / splits --------------------------------------
__global__ void init_state(const float* __restrict__ hid, const float* __restrict__ cur,
                           __half* __restrict__ hsp, float* __restrict__ hf,
                           float* __restrict__ c)
{
    int i = blockIdx.x * blockDim.x + threadIdx.x;
    const int total = Ss * Bsz * Hh;
    if (i >= total) return;
    int l = i / (Bsz * Hh);
    int r = i - l * (Bsz * Hh);
    int b = r >> 8;
    int j = r & 255;
    float v = hid[i];
    size_t dst = (size_t)b * SH + l * Hh + j;
    hsp[dst] = __float2half(v);
    hf[dst]  = v;
    c[dst]   = cur[i];
}

__global__ void conv_x(const float* __restrict__ x, __half* __restrict__ xsp)
{
    int i = blockIdx.x * blockDim.x + threadIdx.x;
    if (i >= Bsz * Dd) return;
    xsp[i] = __float2half(x[i]);
}

// ---------------- fused weight repack (fp32 -> fp16, concat rows) ----------
#define RW1 (Ss * NZS * Dd)
#define RW2 (RW1 + Ss * NU * Hh)
#define RW3 (RW2 + NAG * SH)
#define RW4 (RW3 + Ss * NZS)
#define RW5 (RW4 + Ss * NU)
#define RW6 (RW5 + NLP * FEATK)

__global__ void repack_all(const float* __restrict__ wif, const float* __restrict__ wii,
                           const float* __restrict__ wio, const float* __restrict__ wic,
                           const float* __restrict__ whf, const float* __restrict__ whi,
                           const float* __restrict__ who, const float* __restrict__ whc,
                           const float* __restrict__ bif, const float* __restrict__ bii,
                           const float* __restrict__ bio, const float* __restrict__ bic,
                           const float* __restrict__ bhf, const float* __restrict__ bhi,
                           const float* __restrict__ bho, const float* __restrict__ wlast,
                           __half* __restrict__ WiAll, __half* __restrict__ Whfio,
                           __half* __restrict__ Whc, __half* __restrict__ Wlast,
                           float* __restrict__ biAll, float* __restrict__ bhfio)
{
    int idx = blockIdx.x * blockDim.x + threadIdx.x;
    if (idx < RW1) {
        int k = idx % Dd;
        int r = (idx / Dd) % NZS;
        int l = idx / (Dd * NZS);
        float v;
        if      (r < 256) v = wif[((size_t)l * Hh + r)       * Dd + k];
        else if (r < 512) v = wii[((size_t)l * Hh + r - 256) * Dd + k];
        else if (r < 768) v = wio[((size_t)l * Hh + r - 512) * Dd + k];
        else              v = wic[((size_t)l * Hh + r - 768) * Dd + k];
        WiAll[idx] = __float2half(v);
    } else if (idx < RW2) {
        int t = idx - RW1;
        int k = t % Hh;
        int r = (t / Hh) % NU;
        int l = t / (Hh * NU);
        float v;
        if      (r < 256) v = whf[((size_t)l * Hh + r)       * Hh + k];
        else if (r < 512) v = whi[((size_t)l * Hh + r - 256) * Hh + k];
        else              v = who[((size_t)l * Hh + r - 512) * Hh + k];
        Whfio[t] = __float2half(v);
    } else if (idx < RW3) {
        int t = idx - RW2;
        Whc[t] = __float2half(whc[t]);
    } else if (idx < RW4) {
        int t = idx - RW3;
        int r = t % NZS, l = t / NZS;
        float v;
        if      (r < 256) v = bif[l * Hh + r];
        else if (r < 512) v = bii[l * Hh + r - 256];
        else if (r < 768) v = bio[l * Hh + r - 512];
        else              v = bic[l * Hh + r - 768];
        biAll[t] = v;
    } else if (idx < RW5) {
        int t = idx - RW4;
        int r = t % NU, l = t / NU;
        float v;
        if      (r < 256) v = bhf[l * Hh + r];
        else if (r < 512) v = bhi[l * Hh + r - 256];
        else              v = bho[l * Hh + r - 512];
        bhfio[t] = v;
    } else if (idx < RW6) {
        int t = idx - RW5;
        int r = t / FEATK;
        int k = t - r * FEATK;
        Wlast[t] = (r < OUTN) ? __float2half(wlast[(size_t)r * FEATK + k])
                              : __float2half(0.f);
    }
}

// ---------------- orchestration --------------------------------------------
extern "C" void kernel_launch(void* const* d_in, const int* in_sizes, int n_in,
                              void* d_out, int out_size)
{
    (void)in_sizes; (void)n_in; (void)out_size;
    const float* x    = (const float*)d_in[0];
    const float* hid0 = (const float*)d_in[1];
    const float* cur0 = (const float*)d_in[2];
    const float* Wi_f = (const float*)d_in[3];
    const float* bi_f = (const float*)d_in[4];
    const float* Wi_i = (const float*)d_in[5];
    const float* bi_i = (const float*)d_in[6];
    const float* Wi_o = (const float*)d_in[7];
    const float* bi_o = (const float*)d_in[8];
    const float* Wi_c = (const float*)d_in[9];
    const float* bi_c = (const float*)d_in[10];
    const float* Wi_g = (const float*)d_in[11];
    const float* bi_g = (const float*)d_in[12];
    const float* Wh_f = (const float*)d_in[13];
    const float* bh_f = (const float*)d_in[14];
    const float* Wh_i = (const float*)d_in[15];
    const float* bh_i = (const float*)d_in[16];
    const float* Wh_o = (const float*)d_in[17];
    const float* bh_o = (const float*)d_in[18];
    const float* Wh_g = (const float*)d_in[19];
    const float* bh_g = (const float*)d_in[20];
    const float* Wh_c = (const float*)d_in[21];
    const float* bh_c = (const float*)d_in[22];
    const float* W_last = (const float*)d_in[23];
    const float* b_last = (const float*)d_in[24];
    float* out = (float*)d_out;

    __half *hsp, *xsp, *WiAll, *Whfio, *Whc, *Wlast, *U, *AG, *Z, *Z0, *featf;
    float *hf, *cst, *G2, *G0, *biAll, *bhfio;
    cudaGetSymbolAddress((void**)&hsp,   g_hsp);
    cudaGetSymbolAddress((void**)&hf,    g_hf);
    cudaGetSymbolAddress((void**)&xsp,   g_xsp);
    cudaGetSymbolAddress((void**)&cst,   g_c);
    cudaGetSymbolAddress((void**)&U,     g_U);
    cudaGetSymbolAddress((void**)&AG,    g_AG);
    cudaGetSymbolAddress((void**)&G2,    g_G2);
    cudaGetSymbolAddress((void**)&G0,    g_G0);
    cudaGetSymbolAddress((void**)&Z,     g_Z);
    cudaGetSymbolAddress((void**)&Z0,    g_Z0);
    cudaGetSymbolAddress((void**)&featf, g_featf);
    cudaGetSymbolAddress((void**)&WiAll, g_WiAll);
    cudaGetSymbolAddress((void**)&biAll, g_biAll);
    cudaGetSymbolAddress((void**)&Whfio, g_Whfio);
    cudaGetSymbolAddress((void**)&bhfio, g_bhfio);
    cudaGetSymbolAddress((void**)&Whc,   g_Whc);
    cudaGetSymbolAddress((void**)&Wlast, g_Wlast);

    cudaFuncSetAttribute(gemm256,  cudaFuncAttributeMaxDynamicSharedMemorySize, SMEM_GEMM);
    cudaFuncSetAttribute(gemm_agu, cudaFuncAttributeMaxDynamicSharedMemorySize, SMEM_GEMM);
    cudaFuncSetAttribute(gemm_out, cudaFuncAttributeMaxDynamicSharedMemorySize, SMEM_GEMM);

    const dim3 blk(256);

    // PDL launch attribute (applies to loop kernels)
    cudaLaunchAttribute pat[1];
    pat[0].id = cudaLaunchAttributeProgrammaticStreamSerialization;
    pat[0].val.programmaticStreamSerializationAllowed = 1;
    auto mkcfg = [&](dim3 g, size_t sm) {
        cudaLaunchConfig_t cf;
        cf.gridDim = g;
        cf.blockDim = blk;
        cf.dynamicSmemBytes = sm;
        cf.stream = 0;
        cf.attrs = pat;
        cf.numAttrs = 1;
        return cf;
    };

    // ---- setup (regular launches) ----
    init_state<<<(Ss * Bsz * Hh + 255) / 256, blk>>>(hid0, cur0, hsp, hf, cst);
    conv_x<<<(Bsz * Dd + 255) / 256, blk>>>(x, xsp);
    repack_all<<<(RW6 + 255) / 256, blk>>>(Wi_f, Wi_i, Wi_o, Wi_c,
                                           Wh_f, Wh_i, Wh_o, Wh_c,
                                           bi_f, bi_i, bi_o, bi_c,
                                           bh_f, bh_i, bh_o, W_last,
                                           WiAll, Whfio, Whc, Wlast, biAll, bhfio);
    glog0_kernel<<<(Bsz * 3 * 32 + 255) / 256, blk>>>(x, Wi_g, bi_g, G0);
    // Z0 = x @ Wi[0]^T + bias  (time-invariant)
    gemm256<<<dim3(4, 32, 1), blk, SMEM_GEMM>>>(xsp, Dd, WiAll, Dd,
                                                biAll, Z0, NZS, Dd);

    for (int t = 0; t < REPT; t++) {
        // AG + U + G2 (all read state(t-1))
        {
            cudaLaunchConfig_t cf = mkcfg(dim3(10, 32, 2), SMEM_GEMM);
            cudaLaunchKernelEx(&cf, gemm_agu,
                (const __half*)hsp, (const __half*)Whc, bh_c, AG,
                (const __half*)Whfio, (const float*)bhfio, U,
                (const float*)hf, Wh_g, bh_g, G2);
        }
        // cell0
        {
            cudaLaunchConfig_t cf = mkcfg(dim3(Bsz), 0);
            cudaLaunchKernelEx(&cf, cell_kernel,
                (const __half*)Z0, (const __half*)U, (const __half*)AG,
                (const float*)G2, (const float*)G0,
                (const float*)nullptr, (const float*)nullptr, (const float*)nullptr,
                hsp, hf, cst, (__half*)nullptr, 0, t);
        }
        // Z1
        {
            cudaLaunchConfig_t cf = mkcfg(dim3(4, 32, 1), SMEM_GEMM);
            cudaLaunchKernelEx(&cf, gemm256,
                (const __half*)hsp, (int)SH,
                (const __half*)(WiAll + (size_t)NZS * Dd), (int)Dd,
                (const float*)(biAll + NZS), Z, (int)NZS, (int)Hh);
        }
        // cell1
        {
            cudaLaunchConfig_t cf = mkcfg(dim3(Bsz), 0);
            cudaLaunchKernelEx(&cf, cell_kernel,
                (const __half*)Z, (const __half*)(U + (size_t)Bsz * NU),
                (const __half*)AG, (const float*)G2, (const float*)nullptr,
                (const float*)(Wi_g + (size_t)3 * Dd), (const float*)(bi_g + 3),
                (const float*)hf,
                hsp, hf, cst, (__half*)nullptr, 1, t);
        }
        // Z2
        {
            cudaLaunchConfig_t cf = mkcfg(dim3(4, 32, 1), SMEM_GEMM);
            cudaLaunchKernelEx(&cf, gemm256,
                (const __half*)(hsp + Hh), (int)SH,
                (const __half*)(WiAll + (size_t)2 * NZS * Dd), (int)Dd,
                (const float*)(biAll + 2 * NZS), Z, (int)NZS, (int)Hh);
        }
        // cell2
        {
            __half* fptr = (t < REPT - 1) ? featf : nullptr;
            cudaLaunchConfig_t cf = mkcfg(dim3(Bsz), 0);
            cudaLaunchKernelEx(&cf, cell_kernel,
                (const __half*)Z, (const __half*)(U + (size_t)2 * Bsz * NU),
                (const __half*)AG, (const float*)G2, (const float*)nullptr,
                (const float*)(Wi_g + (size_t)6 * Dd), (const float*)(bi_g + 6),
                (const float*)(hf + Hh),
                hsp, hf, cst, fptr, 2, t);
        }
    }

    // out = sigmoid(feat @ W_last^T + b_last) via HMMA GEMM (N padded to 256)
    {
        cudaLaunchConfig_t cf = mkcfg(dim3(1, 32, 1), SMEM_GEMM);
        cudaLaunchKernelEx(&cf, gemm_out,
            (const __half*)featf, (const __half*)Wlast, b_last, out);
    }
}

// round 16
// speedup vs baseline: 1.3506x; 1.1079x over previous
#include <cuda_runtime.h>
#include <cuda_fp16.h>
#include <math.h>
#include <stdint.h>

// Problem constants
#define Bsz  4096
#define Dd   256
#define Hh   256
#define Ss   3
#define REPT 10
#define OUTN 44
#define SH   768      // S*H
#define NZS  1024     // Z rows: f,i,o,c blocks of 256
#define NU   768
#define NAG  2304     // fused AG: 3 layers x 768 aux rows
#define FEATK 2304    // (REP-1)*H
#define NLP  256      // padded W_last rows

// ---------------- scratch (static device arrays; no cudaMalloc) ------------
__device__ __half g_hsp[(size_t)Bsz * SH];        // fp16 hidden state (h_cat layout)
__device__ __half g_xsp[(size_t)Bsz * Dd];        // fp16 x
__device__ float  g_c[(size_t)Bsz * SH];
__device__ __half g_U[(size_t)Ss * Bsz * NU];     // fp16 preacts
__device__ __half g_AG[(size_t)Bsz * NAG];        // fp16 preacts
__device__ float  g_G2[(size_t)Bsz * 12];         // Wh_g . h_cat + bh_g (9 used)
__device__ float  g_G0[(size_t)Bsz * 3];          // Wi_g[0] . x + bi_g[0]
__device__ __half g_Z[(size_t)Bsz * NZS];         // fp16 preacts
__device__ __half g_Z0[(size_t)Bsz * NZS];
__device__ __half g_featf[(size_t)Bsz * FEATK];   // fp16 features
__device__ __half g_WiAll[(size_t)Ss * NZS * Dd];
__device__ float  g_biAll[Ss * NZS];
__device__ __half g_Whfio[(size_t)Ss * NU * Hh];
__device__ float  g_bhfio[Ss * NU];
__device__ __half g_Whc[(size_t)NAG * SH];
__device__ __half g_Wlast[(size_t)NLP * FEATK];   // padded, rows >=44 zero

// fast activations: MUFU ex2 based, rel err ~1e-6
__device__ __forceinline__ float sigf(float x) {
    return __fdividef(1.0f, 1.0f + __expf(-x));
}
__device__ __forceinline__ float tanhf_fast(float x) {
    return fmaf(2.0f, sigf(2.0f * x), -1.0f);
}

// ---------------- PDL intrinsics --------------------------------------------
__device__ __forceinline__ void pdl_trigger() {
    asm volatile("griddepcontrol.launch_dependents;");
}
__device__ __forceinline__ void pdl_wait() {
    asm volatile("griddepcontrol.wait;" ::: "memory");
}

// ---------------- fp16 HMMA GEMM core: 128x256x64, 3-stage ------------------
#define BM 128
#define BN 256
#define BKE 64
#define SAS 72
#define SA_SZ (BM * SAS)
#define SB_SZ (BN * SAS)
#define STG_E (SA_SZ + SB_SZ)
#define SMEM_GEMM (3 * STG_E * 2)   // 165888 bytes

#define LDSM4(r0,r1,r2,r3,addr) \
  asm volatile("ldmatrix.sync.aligned.m8n8.x4.shared.b16 {%0,%1,%2,%3}, [%4];" \
   : "=r"(r0),"=r"(r1),"=r"(r2),"=r"(r3) : "r"(addr))

#define MMA16816(d, a, b) \
  asm volatile("mma.sync.aligned.m16n8k16.row.col.f32.f16.f16.f32 " \
    "{%0,%1,%2,%3}, {%4,%5,%6,%7}, {%8,%9}, {%0,%1,%2,%3};" \
    : "+f"(d[0]),"+f"(d[1]),"+f"(d[2]),"+f"(d[3]) \
    : "r"(a[0]),"r"(a[1]),"r"(a[2]),"r"(a[3]), "r"(b[0]),"r"(b[1]))

// W tiles (static weights) are prefetched BEFORE pdl_wait; A tiles after.
__device__ __forceinline__ void
gemm_main(const __half* __restrict__ A, int lda,
          const __half* __restrict__ W, int ldw,
          int m0, int n0, int K, float acw[4][8][4])
{
    extern __shared__ __align__(16) __half smem[];
    const int tid  = threadIdx.x;
    const int warp = tid >> 5;
    const int lane = tid & 31;
    const int wm = warp & 1;
    const int wn = warp >> 1;
    const int KT = K / BKE;

#pragma unroll
    for (int mi = 0; mi < 4; mi++)
#pragma unroll
        for (int ni = 0; ni < 8; ni++)
#pragma unroll
            for (int q = 0; q < 4; q++) acw[mi][ni][q] = 0.f;

    auto load_W = [&](int kt, int s) {
        const __half* Wp = W + kt * BKE;
        __half* sb0 = smem + s * STG_E + SA_SZ;
#pragma unroll
        for (int i = 0; i < 8; i++) {
            int idx = tid + i * 256;
            int row = idx >> 3;
            int ch  = idx & 7;
            unsigned sb = (unsigned)__cvta_generic_to_shared(&sb0[row * SAS + ch * 8]);
            const void* gw = Wp + (size_t)(n0 + row) * ldw + ch * 8;
            asm volatile("cp.async.cg.shared.global [%0], [%1], 16;" :: "r"(sb), "l"(gw));
        }
    };
    auto load_A = [&](int kt, int s) {
        const __half* Ap = A + kt * BKE;
        __half* sa0 = smem + s * STG_E;
#pragma unroll
        for (int i = 0; i < 4; i++) {
            int idx = tid + i * 256;
            int row = idx >> 3;
            int ch  = idx & 7;
            unsigned sa = (unsigned)__cvta_generic_to_shared(&sa0[row * SAS + ch * 8]);
            const void* ga = Ap + (size_t)(m0 + row) * lda + ch * 8;
            asm volatile("cp.async.cg.shared.global [%0], [%1], 16;" :: "r"(sa), "l"(ga));
        }
    };
    auto load_tiles = [&](int kt, int s) {
        load_A(kt, s);
        load_W(kt, s);
        asm volatile("cp.async.commit_group;");
    };

    // prologue: W tiles (independent of predecessor) first, then wait, then A
    load_W(0, 0);
    load_W(1, 1);
    pdl_wait();
    load_A(0, 0);
    asm volatile("cp.async.commit_group;");   // g0: W0, W1, A0
    load_A(1, 1);
    asm volatile("cp.async.commit_group;");   // g1: A1

    const int lt  = lane >> 3;
    const int lr  = lane & 7;

    int s = 0;
    for (int kt = 0; kt < KT; kt++) {
        asm volatile("cp.async.wait_group 1;");
        __syncthreads();

        const __half* pa = smem + s * STG_E;
        const __half* pb = pa + SA_SZ;
#pragma unroll
        for (int kq = 0; kq < 4; kq++) {
            const int k0 = kq * 16;
            unsigned af[4][4];
#pragma unroll
            for (int mi = 0; mi < 4; mi++) {
                int mrow = wm * 64 + mi * 16 + (lt & 1) * 8 + lr;
                int kcol = k0 + (lt >> 1) * 8;
                unsigned addr = (unsigned)__cvta_generic_to_shared(&pa[mrow * SAS + kcol]);
                LDSM4(af[mi][0], af[mi][1], af[mi][2], af[mi][3], addr);
            }
            unsigned bf[8][2];
#pragma unroll
            for (int nb = 0; nb < 4; nb++) {
                int nrow = wn * 64 + nb * 16 + (lt >> 1) * 8 + lr;
                int kcol = k0 + (lt & 1) * 8;
                unsigned addr = (unsigned)__cvta_generic_to_shared(&pb[nrow * SAS + kcol]);
                unsigned r0, r1, r2, r3;
                LDSM4(r0, r1, r2, r3, addr);
                bf[nb * 2][0] = r0;     bf[nb * 2][1] = r1;
                bf[nb * 2 + 1][0] = r2; bf[nb * 2 + 1][1] = r3;
            }
#pragma unroll
            for (int mi = 0; mi < 4; mi++)
#pragma unroll
                for (int ni = 0; ni < 8; ni++)
                    MMA16816(acw[mi][ni], af[mi], bf[ni]);
        }
        if (kt + 2 < KT) load_tiles(kt + 2, (s + 2 >= 3) ? s - 1 : s + 2);
        else asm volatile("cp.async.commit_group;");
        if (++s == 3) s = 0;
    }
}

// epilogue: fp32 accum + fp32 bias -> fp16 store (half2 pairs)
__device__ __forceinline__ void
gemm_epi_store(float acw[4][8][4], const float* __restrict__ bz,
               __half* __restrict__ C, int ldc, int m0, int n0)
{
    const int warp = threadIdx.x >> 5;
    const int lane = threadIdx.x & 31;
    const int wm = warp & 1;
    const int wn = warp >> 1;
#pragma unroll
    for (int mi = 0; mi < 4; mi++) {
        const int r0 = m0 + wm * 64 + mi * 16 + (lane >> 2);
#pragma unroll
        for (int ni = 0; ni < 8; ni++) {
            const int cc = n0 + wn * 64 + ni * 8 + (lane & 3) * 2;
            const float* a = acw[mi][ni];
            float b0 = bz[cc], b1 = bz[cc + 1];
            *(__half2*)&C[(size_t)r0 * ldc + cc] =
                __floats2half2_rn(a[0] + b0, a[1] + b1);
            *(__half2*)&C[(size_t)(r0 + 8) * ldc + cc] =
                __floats2half2_rn(a[2] + b0, a[3] + b1);
        }
    }
}

__global__ void __launch_bounds__(256, 1)
gemm256(const __half* __restrict__ A, int lda,
        const __half* __restrict__ W, int ldw,
        const float* __restrict__ bias,
        __half* __restrict__ C, int ldc, int K)
{
    pdl_trigger();
    float acw[4][8][4];
    gemm_main(A, lda, W, ldw, blockIdx.y * BM, blockIdx.x * BN, K, acw);
    gemm_epi_store(acw, bias, C, ldc, blockIdx.y * BM, blockIdx.x * BN);
}

// Final projection: out = sigmoid(feat @ W_last^T + b_last), N padded to 256.
__global__ void __launch_bounds__(256, 1)
gemm_out(const __half* __restrict__ feat,
         const __half* __restrict__ Wl, const float* __restrict__ bl,
         float* __restrict__ out)
{
    pdl_trigger();
    float acw[4][8][4];
    const int m0 = blockIdx.y * BM;
    gemm_main(feat, FEATK, Wl, FEATK, m0, 0, FEATK, acw);

    const int warp = threadIdx.x >> 5;
    const int lane = threadIdx.x & 31;
    const int wm = warp & 1;
    const int wn = warp >> 1;
#pragma unroll
    for (int mi = 0; mi < 4; mi++) {
        const int r0 = m0 + wm * 64 + mi * 16 + (lane >> 2);
#pragma unroll
        for (int ni = 0; ni < 8; ni++) {
            const int cc = wn * 64 + ni * 8 + (lane & 3) * 2;
            if (cc >= OUTN) continue;
            const float* a = acw[mi][ni];
            out[(size_t)r0 * OUTN + cc] = sigf(a[0] + bl[cc]);
            out[(size_t)(r0 + 8) * OUTN + cc] = sigf(a[2] + bl[cc]);
            if (cc + 1 < OUTN) {
                out[(size_t)r0 * OUTN + cc + 1] = sigf(a[1] + bl[cc + 1]);
                out[(size_t)(r0 + 8) * OUTN + cc + 1] = sigf(a[3] + bl[cc + 1]);
            }
        }
    }
}

// Combined AG + U + G2 launch: grid (10, 32, 2).
//   z=0, x<9 : AG tile.  z=1, x<9 : U tile (l=x/3, nt=x%3).  z=1, x==9 : G2.
__global__ void __launch_bounds__(256, 1)
gemm_agu(const __half* __restrict__ hsp,
         const __half* __restrict__ Whc, const float* __restrict__ bhc,
         __half* __restrict__ AG,
         const __half* __restrict__ Whfio, const float* __restrict__ bhfio,
         __half* __restrict__ U,
         const float* __restrict__ whg, const float* __restrict__ bhg,
         float* __restrict__ G2)
{
    pdl_trigger();
    if (blockIdx.z == 0) {
        if (blockIdx.x >= 9) { pdl_wait(); return; }
        float acw[4][8][4];
        gemm_main(hsp, SH, Whc, SH, blockIdx.y * BM, blockIdx.x * BN, SH, acw);
        gemm_epi_store(acw, bhc, AG, NAG, blockIdx.y * BM, blockIdx.x * BN);
    } else if (blockIdx.x < 9) {
        const int l  = blockIdx.x / 3;
        const int xt = blockIdx.x - l * 3;
        float acw[4][8][4];
        gemm_main(hsp + l * Hh, SH, Whfio + (size_t)l * NU * Hh, Hh,
                  blockIdx.y * BM, xt * BN, Hh, acw);
        gemm_epi_store(acw, bhfio + l * NU, U + (size_t)l * Bsz * NU, NU,
                       blockIdx.y * BM, xt * BN);
    } else {
        // G2: 9 dots of 768 per row (reads fp16 h_cat(t-1)), 128 rows per m-tile
        pdl_wait();
        const int m0 = blockIdx.y * BM;
        const int warp = threadIdx.x >> 5;
        const int lane = threadIdx.x & 31;
        for (int rr = 0; rr < 16; rr++) {
            int row = m0 + warp * 16 + rr;
            const __half* hr = hsp + (size_t)row * SH;
            float p[9];
#pragma unroll
            for (int o = 0; o < 9; o++) p[o] = 0.f;
            for (int i = 0; i < 24; i++) {
                int k = lane + 32 * i;
                float hv = __half2float(hr[k]);
#pragma unroll
                for (int o = 0; o < 9; o++) p[o] += hv * whg[o * SH + k];
            }
#pragma unroll
            for (int o = 0; o < 9; o++) {
#pragma unroll
                for (int off = 16; off; off >>= 1)
                    p[o] += __shfl_xor_sync(0xFFFFFFFFu, p[o], off);
            }
            if (lane == 0) {
#pragma unroll
                for (int o = 0; o < 9; o++)
                    G2[(size_t)row * 12 + o] = p[o] + bhg[o];
            }
        }
    }
}

// ---------------- per-layer LSTM cell (block = one batch row) ---------------
__global__ void __launch_bounds__(256)
cell_kernel(const __half* __restrict__ Z, const __half* __restrict__ U,
            const __half* __restrict__ AG, const float* __restrict__ G2,
            const float* __restrict__ G0,
            const float* __restrict__ wig3, const float* __restrict__ big3,
            const __half* __restrict__ hin,
            __half* __restrict__ hsp, float* __restrict__ c,
            __half* __restrict__ featf, int l, int t)
{
    pdl_trigger();
    pdl_wait();
    const int b = blockIdx.x;
    const int j = threadIdx.x;
    const int warp = j >> 5;
    const int lane = j & 31;
    __shared__ float red[3][8];

    float gin0, gin1, gin2;
    if (l == 0) {
        gin0 = G0[(size_t)b * 3 + 0];
        gin1 = G0[(size_t)b * 3 + 1];
        gin2 = G0[(size_t)b * 3 + 2];
    } else {
        float iv = __half2float(hin[(size_t)b * SH + j]);
        float p0 = iv * wig3[j];
        float p1 = iv * wig3[256 + j];
        float p2 = iv * wig3[512 + j];
#pragma unroll
        for (int off = 16; off; off >>= 1) {
            p0 += __shfl_xor_sync(0xFFFFFFFFu, p0, off);
            p1 += __shfl_xor_sync(0xFFFFFFFFu, p1, off);
            p2 += __shfl_xor_sync(0xFFFFFFFFu, p2, off);
        }
        if (lane == 0) { red[0][warp] = p0; red[1][warp] = p1; red[2][warp] = p2; }
        __syncthreads();
        float s0 = 0.f, s1 = 0.f, s2 = 0.f;
#pragma unroll
        for (int w = 0; w < 8; w++) { s0 += red[0][w]; s1 += red[1][w]; s2 += red[2][w]; }
        gin0 = s0 + big3[0];
        gin1 = s1 + big3[1];
        gin2 = s2 + big3[2];
    }

    const float* g2p = G2 + (size_t)b * 12 + l * 3;
    float g0 = sigf(gin0 + g2p[0]);
    float g1 = sigf(gin1 + g2p[1]);
    float g2v = sigf(gin2 + g2p[2]);

    const __half* Zb = Z + (size_t)b * NZS;
    const __half* Ub = U + (size_t)b * NU;
    const __half* Gb = AG + (size_t)b * NAG + l * SH;
    float aux = g0 * __half2float(Gb[j]) + g1 * __half2float(Gb[256 + j])
              + g2v * __half2float(Gb[512 + j]);

    float fg = sigf(__half2float(Zb[j])       + __half2float(Ub[j]));
    float ig = sigf(__half2float(Zb[256 + j]) + __half2float(Ub[256 + j]));
    float og = sigf(__half2float(Zb[512 + j]) + __half2float(Ub[512 + j]));
    float ct = tanhf_fast(__half2float(Zb[768 + j]) + aux);

    size_t sidx = (size_t)b * SH + l * Hh + j;
    float cn = fg * c[sidx] + ig * ct;
    float hn = og * cn;
    c[sidx] = cn;
    __half hh = __float2half(hn);
    hsp[sidx] = hh;
    if (featf) featf[(size_t)b * FEATK + t * Hh + j] = hh;
}

// ---------------- small fp32 dot kernels ------------------------------------
__global__ void glog0_kernel(const float* __restrict__ x,
                             const float* __restrict__ wig,
                             const float* __restrict__ big,
                             float* __restrict__ G0)
{
    int gw = (blockIdx.x * blockDim.x + threadIdx.x) >> 5;
    int lane = threadIdx.x & 31;
    if (gw >= Bsz * 3) return;
    int b = gw / 3;
    int r = gw - b * 3;
    const float* xr = x + (size_t)b * Dd;
    const float* wr = wig + (size_t)r * Dd;
    float sum = 0.f;
#pragma unroll 4
    for (int k = lane; k < Dd; k += 32) sum += xr[k] * wr[k];
#pragma unroll
    for (int off = 16; off; off >>= 1) sum += __shfl_xor_sync(0xFFFFFFFFu, sum, off);
    if (lane == 0) G0[(size_t)b * 3 + r] = sum + big[r];
}

// ---------------- state init / splits --------------------------------------
__global__ void init_state(const float* __restrict__ hid, const float* __restrict__ cur,
                           __half* __restrict__ hsp, float* __restrict__ c)
{
    int i = blockIdx.x * blockDim.x + threadIdx.x;
    const int total = Ss * Bsz * Hh;
    if (i >= total) return;
    int l = i / (Bsz * Hh);
    int r = i - l * (Bsz * Hh);
    int b = r >> 8;
    int j = r & 255;
    size_t dst = (size_t)b * SH + l * Hh + j;
    hsp[dst] = __float2half(hid[i]);
    c[dst]   = cur[i];
}

__global__ void conv_x(const float* __restrict__ x, __half* __restrict__ xsp)
{
    int i = blockIdx.x * blockDim.x + threadIdx.x;
    if (i >= Bsz * Dd) return;
    xsp[i] = __float2half(x[i]);
}

// ---------------- fused weight repack (fp32 -> fp16, concat rows) ----------
#define RW1 (Ss * NZS * Dd)
#define RW2 (RW1 + Ss * NU * Hh)
#define RW3 (RW2 + NAG * SH)
#define RW4 (RW3 + Ss * NZS)
#define RW5 (RW4 + Ss * NU)
#define RW6 (RW5 + NLP * FEATK)

__global__ void repack_all(const float* __restrict__ wif, const float* __restrict__ wii,
                           const float* __restrict__ wio, const float* __restrict__ wic,
                           const float* __restrict__ whf, const float* __restrict__ whi,
                           const float* __restrict__ who, const float* __restrict__ whc,
                           const float* __restrict__ bif, const float* __restrict__ bii,
                           const float* __restrict__ bio, const float* __restrict__ bic,
                           const float* __restrict__ bhf, const float* __restrict__ bhi,
                           const float* __restrict__ bho, const float* __restrict__ wlast,
                           __half* __restrict__ WiAll, __half* __restrict__ Whfio,
                           __half* __restrict__ Whc, __half* __restrict__ Wlast,
                           float* __restrict__ biAll, float* __restrict__ bhfio)
{
    int idx = blockIdx.x * blockDim.x + threadIdx.x;
    if (idx < RW1) {
        int k = idx % Dd;
        int r = (idx / Dd) % NZS;
        int l = idx / (Dd * NZS);
        float v;
        if      (r < 256) v = wif[((size_t)l * Hh + r)       * Dd + k];
        else if (r < 512) v = wii[((size_t)l * Hh + r - 256) * Dd + k];
        else if (r < 768) v = wio[((size_t)l * Hh + r - 512) * Dd + k];
        else              v = wic[((size_t)l * Hh + r - 768) * Dd + k];
        WiAll[idx] = __float2half(v);
    } else if (idx < RW2) {
        int t = idx - RW1;
        int k = t % Hh;
        int r = (t / Hh) % NU;
        int l = t / (Hh * NU);
        float v;
        if      (r < 256) v = whf[((size_t)l * Hh + r)       * Hh + k];
        else if (r < 512) v = whi[((size_t)l * Hh + r - 256) * Hh + k];
        else              v = who[((size_t)l * Hh + r - 512) * Hh + k];
        Whfio[t] = __float2half(v);
    } else if (idx < RW3) {
        int t = idx - RW2;
        Whc[t] = __float2half(whc[t]);
    } else if (idx < RW4) {
        int t = idx - RW3;
        int r = t % NZS, l = t / NZS;
        float v;
        if      (r < 256) v = bif[l * Hh + r];
        else if (r < 512) v = bii[l * Hh + r - 256];
        else if (r < 768) v = bio[l * Hh + r - 512];
        else              v = bic[l * Hh + r - 768];
        biAll[t] = v;
    } else if (idx < RW5) {
        int t = idx - RW4;
        int r = t % NU, l = t / NU;
        float v;
        if      (r < 256) v = bhf[l * Hh + r];
        else if (r < 512) v = bhi[l * Hh + r - 256];
        else              v = bho[l * Hh + r - 512];
        bhfio[t] = v;
    } else if (idx < RW6) {
        int t = idx - RW5;
        int r = t / FEATK;
        int k = t - r * FEATK;
        Wlast[t] = (r < OUTN) ? __float2half(wlast[(size_t)r * FEATK + k])
                              : __float2half(0.f);
    }
}

// ---------------- orchestration --------------------------------------------
extern "C" void kernel_launch(void* const* d_in, const int* in_sizes, int n_in,
                              void* d_out, int out_size)
{
    (void)in_sizes; (void)n_in; (void)out_size;
    const float* x    = (const float*)d_in[0];
    const float* hid0 = (const float*)d_in[1];
    const float* cur0 = (const float*)d_in[2];
    const float* Wi_f = (const float*)d_in[3];
    const float* bi_f = (const float*)d_in[4];
    const float* Wi_i = (const float*)d_in[5];
    const float* bi_i = (const float*)d_in[6];
    const float* Wi_o = (const float*)d_in[7];
    const float* bi_o = (const float*)d_in[8];
    const float* Wi_c = (const float*)d_in[9];
    const float* bi_c = (const float*)d_in[10];
    const float* Wi_g = (const float*)d_in[11];
    const float* bi_g = (const float*)d_in[12];
    const float* Wh_f = (const float*)d_in[13];
    const float* bh_f = (const float*)d_in[14];
    const float* Wh_i = (const float*)d_in[15];
    const float* bh_i = (const float*)d_in[16];
    const float* Wh_o = (const float*)d_in[17];
    const float* bh_o = (const float*)d_in[18];
    const float* Wh_g = (const float*)d_in[19];
    const float* bh_g = (const float*)d_in[20];
    const float* Wh_c = (const float*)d_in[21];
    const float* bh_c = (const float*)d_in[22];
    const float* W_last = (const float*)d_in[23];
    const float* b_last = (const float*)d_in[24];
    float* out = (float*)d_out;

    __half *hsp, *xsp, *WiAll, *Whfio, *Whc, *Wlast, *U, *AG, *Z, *Z0, *featf;
    float *cst, *G2, *G0, *biAll, *bhfio;
    cudaGetSymbolAddress((void**)&hsp,   g_hsp);
    cudaGetSymbolAddress((void**)&xsp,   g_xsp);
    cudaGetSymbolAddress((void**)&cst,   g_c);
    cudaGetSymbolAddress((void**)&U,     g_U);
    cudaGetSymbolAddress((void**)&AG,    g_AG);
    cudaGetSymbolAddress((void**)&G2,    g_G2);
    cudaGetSymbolAddress((void**)&G0,    g_G0);
    cudaGetSymbolAddress((void**)&Z,     g_Z);
    cudaGetSymbolAddress((void**)&Z0,    g_Z0);
    cudaGetSymbolAddress((void**)&featf, g_featf);
    cudaGetSymbolAddress((void**)&WiAll, g_WiAll);
    cudaGetSymbolAddress((void**)&biAll, g_biAll);
    cudaGetSymbolAddress((void**)&Whfio, g_Whfio);
    cudaGetSymbolAddress((void**)&bhfio, g_bhfio);
    cudaGetSymbolAddress((void**)&Whc,   g_Whc);
    cudaGetSymbolAddress((void**)&Wlast, g_Wlast);

    cudaFuncSetAttribute(gemm256,  cudaFuncAttributeMaxDynamicSharedMemorySize, SMEM_GEMM);
    cudaFuncSetAttribute(gemm_agu, cudaFuncAttributeMaxDynamicSharedMemorySize, SMEM_GEMM);
    cudaFuncSetAttribute(gemm_out, cudaFuncAttributeMaxDynamicSharedMemorySize, SMEM_GEMM);

    const dim3 blk(256);

    // PDL launch attribute (applies to loop kernels)
    cudaLaunchAttribute pat[1];
    pat[0].id = cudaLaunchAttributeProgrammaticStreamSerialization;
    pat[0].val.programmaticStreamSerializationAllowed = 1;
    auto mkcfg = [&](dim3 g, size_t sm) {
        cudaLaunchConfig_t cf;
        cf.gridDim = g;
        cf.blockDim = blk;
        cf.dynamicSmemBytes = sm;
        cf.stream = 0;
        cf.attrs = pat;
        cf.numAttrs = 1;
        return cf;
    };

    // ---- setup (regular launches) ----
    init_state<<<(Ss * Bsz * Hh + 255) / 256, blk>>>(hid0, cur0, hsp, cst);
    conv_x<<<(Bsz * Dd + 255) / 256, blk>>>(x, xsp);
    repack_all<<<(RW6 + 255) / 256, blk>>>(Wi_f, Wi_i, Wi_o, Wi_c,
                                           Wh_f, Wh_i, Wh_o, Wh_c,
                                           bi_f, bi_i, bi_o, bi_c,
                                           bh_f, bh_i, bh_o, W_last,
                                           WiAll, Whfio, Whc, Wlast, biAll, bhfio);
    glog0_kernel<<<(Bsz * 3 * 32 + 255) / 256, blk>>>(x, Wi_g, bi_g, G0);
    // Z0 = x @ Wi[0]^T + bias  (time-invariant)
    gemm256<<<dim3(4, 32, 1), blk, SMEM_GEMM>>>(xsp, Dd, WiAll, Dd,
                                                biAll, Z0, NZS, Dd);

    for (int t = 0; t < REPT; t++) {
        // AG + U + G2 (all read state(t-1))
        {
            cudaLaunchConfig_t cf = mkcfg(dim3(10, 32, 2), SMEM_GEMM);
            cudaLaunchKernelEx(&cf, gemm_agu,
                (const __half*)hsp, (const __half*)Whc, bh_c, AG,
                (const __half*)Whfio, (const float*)bhfio, U,
                Wh_g, bh_g, G2);
        }
        // cell0
        {
            cudaLaunchConfig_t cf = mkcfg(dim3(Bsz), 0);
            cudaLaunchKernelEx(&cf, cell_kernel,
                (const __half*)Z0, (const __half*)U, (const __half*)AG,
                (const float*)G2, (const float*)G0,
                (const float*)nullptr, (const float*)nullptr, (const __half*)nullptr,
                hsp, cst, (__half*)nullptr, 0, t);
        }
        // Z1
        {
            cudaLaunchConfig_t cf = mkcfg(dim3(4, 32, 1), SMEM_GEMM);
            cudaLaunchKernelEx(&cf, gemm256,
                (const __half*)hsp, (int)SH,
                (const __half*)(WiAll + (size_t)NZS * Dd), (int)Dd,
                (const float*)(biAll + NZS), Z, (int)NZS, (int)Hh);
        }
        // cell1
        {
            cudaLaunchConfig_t cf = mkcfg(dim3(Bsz), 0);
            cudaLaunchKernelEx(&cf, cell_kernel,
                (const __half*)Z, (const __half*)(U + (size_t)Bsz * NU),
                (const __half*)AG, (const float*)G2, (const float*)nullptr,
                (const float*)(Wi_g + (size_t)3 * Dd), (const float*)(bi_g + 3),
                (const __half*)hsp,
                hsp, cst, (__half*)nullptr, 1, t);
        }
        // Z2
        {
            cudaLaunchConfig_t cf = mkcfg(dim3(4, 32, 1), SMEM_GEMM);
            cudaLaunchKernelEx(&cf, gemm256,
                (const __half*)(hsp + Hh), (int)SH,
                (const __half*)(WiAll + (size_t)2 * NZS * Dd), (int)Dd,
                (const float*)(biAll + 2 * NZS), Z, (int)NZS, (int)Hh);
        }
        // cell2
        {
            __half* fptr = (t < REPT - 1) ? featf : nullptr;
            cudaLaunchConfig_t cf = mkcfg(dim3(Bsz), 0);
            cudaLaunchKernelEx(&cf, cell_kernel,
                (const __half*)Z, (const __half*)(U + (size_t)2 * Bsz * NU),
                (const __half*)AG, (const float*)G2, (const float*)nullptr,
                (const float*)(Wi_g + (size_t)6 * Dd), (const float*)(bi_g + 6),
                (const __half*)(hsp + Hh),
                hsp, cst, fptr, 2, t);
        }
    }

    // out = sigmoid(feat @ W_last^T + b_last) via HMMA GEMM (N padded to 256)
    {
        cudaLaunchConfig_t cf = mkcfg(dim3(1, 32, 1), SMEM_GEMM);
        cudaLaunchKernelEx(&cf, gemm_out,
            (const __half*)featf, (const __half*)Wlast, b_last, out);
    }
}

// round 17
// speedup vs baseline: 1.4387x; 1.0652x over previous
#include <cuda_runtime.h>
#include <cuda_fp16.h>
#include <math.h>
#include <stdint.h>

// Problem constants
#define Bsz  4096
#define Dd   256
#define Hh   256
#define Ss   3
#define REPT 10
#define OUTN 44
#define SH   768      // S*H
#define NZS  1024     // Z rows: f,i,o,c blocks of 256
#define NU   768
#define NAG  2304     // fused AG: 3 layers x 768 aux rows
#define FEATK 2304    // (REP-1)*H
#define NLP  256      // padded W_last rows
#define KZU  512      // fused ZU GEMM K: [h(l-1)(t) | h(l)(t-1)]

// ---------------- scratch (static device arrays; no cudaMalloc) ------------
__device__ __half g_hsp[(size_t)Bsz * SH];        // fp16 hidden state (h_cat layout)
__device__ __half g_xsp[(size_t)Bsz * Dd];        // fp16 x
__device__ float  g_c[(size_t)Bsz * SH];
__device__ __half g_U[(size_t)Bsz * NU];          // fp16 U preacts (layer 0 only)
__device__ __half g_AG[(size_t)Bsz * NAG];        // fp16 preacts
__device__ float  g_G2[(size_t)Bsz * 12];         // Wh_g . h_cat + bh_g (9 used)
__device__ float  g_G0[(size_t)Bsz * 3];          // Wi_g[0] . x + bi_g[0]
__device__ __half g_Z[(size_t)Bsz * NZS];         // fp16 preacts
__device__ __half g_Z0[(size_t)Bsz * NZS];
__device__ __half g_featf[(size_t)Bsz * FEATK];   // fp16 features
__device__ __half g_WiAll[(size_t)Ss * NZS * Dd];
__device__ float  g_biAll[Ss * NZS];
__device__ __half g_Whfio[(size_t)NU * Hh];       // layer 0 only
__device__ float  g_bhfio[NU];                    // layer 0 only
__device__ __half g_Whc[(size_t)NAG * SH];
__device__ __half g_Wlast[(size_t)NLP * FEATK];   // padded, rows >=44 zero
__device__ __half g_WZU[(size_t)2 * NZS * KZU];   // layers 1,2: [Wi | Whfio(pad)]
__device__ float  g_biZU[2 * NZS];                // combined bi + bh biases

// fast activations: MUFU ex2 based, rel err ~1e-6
__device__ __forceinline__ float sigf(float x) {
    return __fdividef(1.0f, 1.0f + __expf(-x));
}
__device__ __forceinline__ float tanhf_fast(float x) {
    return fmaf(2.0f, sigf(2.0f * x), -1.0f);
}

// ---------------- PDL intrinsics --------------------------------------------
__device__ __forceinline__ void pdl_trigger() {
    asm volatile("griddepcontrol.launch_dependents;");
}
__device__ __forceinline__ void pdl_wait() {
    asm volatile("griddepcontrol.wait;" ::: "memory");
}

// ---------------- fp16 HMMA GEMM core: 128x256x64, 3-stage ------------------
#define BM 128
#define BN 256
#define BKE 64
#define SAS 72
#define SA_SZ (BM * SAS)
#define SB_SZ (BN * SAS)
#define STG_E (SA_SZ + SB_SZ)
#define SMEM_GEMM (3 * STG_E * 2)   // 165888 bytes

#define LDSM4(r0,r1,r2,r3,addr) \
  asm volatile("ldmatrix.sync.aligned.m8n8.x4.shared.b16 {%0,%1,%2,%3}, [%4];" \
   : "=r"(r0),"=r"(r1),"=r"(r2),"=r"(r3) : "r"(addr))

#define MMA16816(d, a, b) \
  asm volatile("mma.sync.aligned.m16n8k16.row.col.f32.f16.f16.f32 " \
    "{%0,%1,%2,%3}, {%4,%5,%6,%7}, {%8,%9}, {%0,%1,%2,%3};" \
    : "+f"(d[0]),"+f"(d[1]),"+f"(d[2]),"+f"(d[3]) \
    : "r"(a[0]),"r"(a[1]),"r"(a[2]),"r"(a[3]), "r"(b[0]),"r"(b[1]))

// W tiles (static weights) are prefetched BEFORE pdl_wait; A tiles after.
__device__ __forceinline__ void
gemm_main(const __half* __restrict__ A, int lda,
          const __half* __restrict__ W, int ldw,
          int m0, int n0, int K, float acw[4][8][4])
{
    extern __shared__ __align__(16) __half smem[];
    const int tid  = threadIdx.x;
    const int warp = tid >> 5;
    const int lane = tid & 31;
    const int wm = warp & 1;
    const int wn = warp >> 1;
    const int KT = K / BKE;

#pragma unroll
    for (int mi = 0; mi < 4; mi++)
#pragma unroll
        for (int ni = 0; ni < 8; ni++)
#pragma unroll
            for (int q = 0; q < 4; q++) acw[mi][ni][q] = 0.f;

    auto load_W = [&](int kt, int s) {
        const __half* Wp = W + kt * BKE;
        __half* sb0 = smem + s * STG_E + SA_SZ;
#pragma unroll
        for (int i = 0; i < 8; i++) {
            int idx = tid + i * 256;
            int row = idx >> 3;
            int ch  = idx & 7;
            unsigned sb = (unsigned)__cvta_generic_to_shared(&sb0[row * SAS + ch * 8]);
            const void* gw = Wp + (size_t)(n0 + row) * ldw + ch * 8;
            asm volatile("cp.async.cg.shared.global [%0], [%1], 16;" :: "r"(sb), "l"(gw));
        }
    };
    auto load_A = [&](int kt, int s) {
        const __half* Ap = A + kt * BKE;
        __half* sa0 = smem + s * STG_E;
#pragma unroll
        for (int i = 0; i < 4; i++) {
            int idx = tid + i * 256;
            int row = idx >> 3;
            int ch  = idx & 7;
            unsigned sa = (unsigned)__cvta_generic_to_shared(&sa0[row * SAS + ch * 8]);
            const void* ga = Ap + (size_t)(m0 + row) * lda + ch * 8;
            asm volatile("cp.async.cg.shared.global [%0], [%1], 16;" :: "r"(sa), "l"(ga));
        }
    };
    auto load_tiles = [&](int kt, int s) {
        load_A(kt, s);
        load_W(kt, s);
        asm volatile("cp.async.commit_group;");
    };

    // prologue: W tiles (independent of predecessor) first, then wait, then A
    load_W(0, 0);
    load_W(1, 1);
    pdl_wait();
    load_A(0, 0);
    asm volatile("cp.async.commit_group;");   // g0: W0, W1, A0
    load_A(1, 1);
    asm volatile("cp.async.commit_group;");   // g1: A1

    const int lt  = lane >> 3;
    const int lr  = lane & 7;

    int s = 0;
    for (int kt = 0; kt < KT; kt++) {
        asm volatile("cp.async.wait_group 1;");
        __syncthreads();

        const __half* pa = smem + s * STG_E;
        const __half* pb = pa + SA_SZ;
#pragma unroll
        for (int kq = 0; kq < 4; kq++) {
            const int k0 = kq * 16;
            unsigned af[4][4];
#pragma unroll
            for (int mi = 0; mi < 4; mi++) {
                int mrow = wm * 64 + mi * 16 + (lt & 1) * 8 + lr;
                int kcol = k0 + (lt >> 1) * 8;
                unsigned addr = (unsigned)__cvta_generic_to_shared(&pa[mrow * SAS + kcol]);
                LDSM4(af[mi][0], af[mi][1], af[mi][2], af[mi][3], addr);
            }
            unsigned bf[8][2];
#pragma unroll
            for (int nb = 0; nb < 4; nb++) {
                int nrow = wn * 64 + nb * 16 + (lt >> 1) * 8 + lr;
                int kcol = k0 + (lt & 1) * 8;
                unsigned addr = (unsigned)__cvta_generic_to_shared(&pb[nrow * SAS + kcol]);
                unsigned r0, r1, r2, r3;
                LDSM4(r0, r1, r2, r3, addr);
                bf[nb * 2][0] = r0;     bf[nb * 2][1] = r1;
                bf[nb * 2 + 1][0] = r2; bf[nb * 2 + 1][1] = r3;
            }
#pragma unroll
            for (int mi = 0; mi < 4; mi++)
#pragma unroll
                for (int ni = 0; ni < 8; ni++)
                    MMA16816(acw[mi][ni], af[mi], bf[ni]);
        }
        if (kt + 2 < KT) load_tiles(kt + 2, (s + 2 >= 3) ? s - 1 : s + 2);
        else asm volatile("cp.async.commit_group;");
        if (++s == 3) s = 0;
    }
}

// epilogue: fp32 accum + fp32 bias -> fp16 store (half2 pairs)
__device__ __forceinline__ void
gemm_epi_store(float acw[4][8][4], const float* __restrict__ bz,
               __half* __restrict__ C, int ldc, int m0, int n0)
{
    const int warp = threadIdx.x >> 5;
    const int lane = threadIdx.x & 31;
    const int wm = warp & 1;
    const int wn = warp >> 1;
#pragma unroll
    for (int mi = 0; mi < 4; mi++) {
        const int r0 = m0 + wm * 64 + mi * 16 + (lane >> 2);
#pragma unroll
        for (int ni = 0; ni < 8; ni++) {
            const int cc = n0 + wn * 64 + ni * 8 + (lane & 3) * 2;
            const float* a = acw[mi][ni];
            float b0 = bz[cc], b1 = bz[cc + 1];
            *(__half2*)&C[(size_t)r0 * ldc + cc] =
                __floats2half2_rn(a[0] + b0, a[1] + b1);
            *(__half2*)&C[(size_t)(r0 + 8) * ldc + cc] =
                __floats2half2_rn(a[2] + b0, a[3] + b1);
        }
    }
}

__global__ void __launch_bounds__(256, 1)
gemm256(const __half* __restrict__ A, int lda,
        const __half* __restrict__ W, int ldw,
        const float* __restrict__ bias,
        __half* __restrict__ C, int ldc, int K)
{
    pdl_trigger();
    float acw[4][8][4];
    gemm_main(A, lda, W, ldw, blockIdx.y * BM, blockIdx.x * BN, K, acw);
    gemm_epi_store(acw, bias, C, ldc, blockIdx.y * BM, blockIdx.x * BN);
}

// Final projection: out = sigmoid(feat @ W_last^T + b_last), N padded to 256.
__global__ void __launch_bounds__(256, 1)
gemm_out(const __half* __restrict__ feat,
         const __half* __restrict__ Wl, const float* __restrict__ bl,
         float* __restrict__ out)
{
    pdl_trigger();
    float acw[4][8][4];
    const int m0 = blockIdx.y * BM;
    gemm_main(feat, FEATK, Wl, FEATK, m0, 0, FEATK, acw);

    const int warp = threadIdx.x >> 5;
    const int lane = threadIdx.x & 31;
    const int wm = warp & 1;
    const int wn = warp >> 1;
#pragma unroll
    for (int mi = 0; mi < 4; mi++) {
        const int r0 = m0 + wm * 64 + mi * 16 + (lane >> 2);
#pragma unroll
        for (int ni = 0; ni < 8; ni++) {
            const int cc = wn * 64 + ni * 8 + (lane & 3) * 2;
            if (cc >= OUTN) continue;
            const float* a = acw[mi][ni];
            out[(size_t)r0 * OUTN + cc] = sigf(a[0] + bl[cc]);
            out[(size_t)(r0 + 8) * OUTN + cc] = sigf(a[2] + bl[cc]);
            if (cc + 1 < OUTN) {
                out[(size_t)r0 * OUTN + cc + 1] = sigf(a[1] + bl[cc + 1]);
                out[(size_t)(r0 + 8) * OUTN + cc + 1] = sigf(a[3] + bl[cc + 1]);
            }
        }
    }
}

// Combined AG + U0 + G2 launch: grid (13, 32).
//   x<9 : AG tile.  9<=x<12 : U0 tile (layer 0).  x==12 : G2.
__global__ void __launch_bounds__(256, 1)
gemm_agu(const __half* __restrict__ hsp,
         const __half* __restrict__ Whc, const float* __restrict__ bhc,
         __half* __restrict__ AG,
         const __half* __restrict__ Whfio0, const float* __restrict__ bhfio0,
         __half* __restrict__ U,
         const float* __restrict__ whg, const float* __restrict__ bhg,
         float* __restrict__ G2)
{
    pdl_trigger();
    if (blockIdx.x < 9) {
        float acw[4][8][4];
        gemm_main(hsp, SH, Whc, SH, blockIdx.y * BM, blockIdx.x * BN, SH, acw);
        gemm_epi_store(acw, bhc, AG, NAG, blockIdx.y * BM, blockIdx.x * BN);
    } else if (blockIdx.x < 12) {
        const int xt = blockIdx.x - 9;
        float acw[4][8][4];
        gemm_main(hsp, SH, Whfio0, Hh, blockIdx.y * BM, xt * BN, Hh, acw);
        gemm_epi_store(acw, bhfio0, U, NU, blockIdx.y * BM, xt * BN);
    } else {
        // G2: 9 dots of 768 per row (reads fp16 h_cat(t-1)), 128 rows per m-tile
        pdl_wait();
        const int m0 = blockIdx.y * BM;
        const int warp = threadIdx.x >> 5;
        const int lane = threadIdx.x & 31;
        for (int rr = 0; rr < 16; rr++) {
            int row = m0 + warp * 16 + rr;
            const __half* hr = hsp + (size_t)row * SH;
            float p[9];
#pragma unroll
            for (int o = 0; o < 9; o++) p[o] = 0.f;
            for (int i = 0; i < 24; i++) {
                int k = lane + 32 * i;
                float hv = __half2float(hr[k]);
#pragma unroll
                for (int o = 0; o < 9; o++) p[o] += hv * whg[o * SH + k];
            }
#pragma unroll
            for (int o = 0; o < 9; o++) {
#pragma unroll
                for (int off = 16; off; off >>= 1)
                    p[o] += __shfl_xor_sync(0xFFFFFFFFu, p[o], off);
            }
            if (lane == 0) {
#pragma unroll
                for (int o = 0; o < 9; o++)
                    G2[(size_t)row * 12 + o] = p[o] + bhg[o];
            }
        }
    }
}

// ---------------- per-layer LSTM cell (block = one batch row) ---------------
// l==0: Z has input preacts only, add U (layer-0 recurrent). l>0: Z already
// contains Z+U+both biases (fused ZU GEMM) -> no U.
__global__ void __launch_bounds__(256)
cell_kernel(const __half* __restrict__ Z, const __half* __restrict__ U,
            const __half* __restrict__ AG, const float* __restrict__ G2,
            const float* __restrict__ G0,
            const float* __restrict__ wig3, const float* __restrict__ big3,
            const __half* __restrict__ hin,
            __half* __restrict__ hsp, float* __restrict__ c,
            __half* __restrict__ featf, int l, int t)
{
    pdl_trigger();
    pdl_wait();
    const int b = blockIdx.x;
    const int j = threadIdx.x;
    const int warp = j >> 5;
    const int lane = j & 31;
    __shared__ float red[3][8];

    float gin0, gin1, gin2;
    if (l == 0) {
        gin0 = G0[(size_t)b * 3 + 0];
        gin1 = G0[(size_t)b * 3 + 1];
        gin2 = G0[(size_t)b * 3 + 2];
    } else {
        float iv = __half2float(hin[(size_t)b * SH + j]);
        float p0 = iv * wig3[j];
        float p1 = iv * wig3[256 + j];
        float p2 = iv * wig3[512 + j];
#pragma unroll
        for (int off = 16; off; off >>= 1) {
            p0 += __shfl_xor_sync(0xFFFFFFFFu, p0, off);
            p1 += __shfl_xor_sync(0xFFFFFFFFu, p1, off);
            p2 += __shfl_xor_sync(0xFFFFFFFFu, p2, off);
        }
        if (lane == 0) { red[0][warp] = p0; red[1][warp] = p1; red[2][warp] = p2; }
        __syncthreads();
        float s0 = 0.f, s1 = 0.f, s2 = 0.f;
#pragma unroll
        for (int w = 0; w < 8; w++) { s0 += red[0][w]; s1 += red[1][w]; s2 += red[2][w]; }
        gin0 = s0 + big3[0];
        gin1 = s1 + big3[1];
        gin2 = s2 + big3[2];
    }

    const float* g2p = G2 + (size_t)b * 12 + l * 3;
    float g0 = sigf(gin0 + g2p[0]);
    float g1 = sigf(gin1 + g2p[1]);
    float g2v = sigf(gin2 + g2p[2]);

    const __half* Zb = Z + (size_t)b * NZS;
    const __half* Gb = AG + (size_t)b * NAG + l * SH;
    float aux = g0 * __half2float(Gb[j]) + g1 * __half2float(Gb[256 + j])
              + g2v * __half2float(Gb[512 + j]);

    float fp = __half2float(Zb[j]);
    float ip = __half2float(Zb[256 + j]);
    float op = __half2float(Zb[512 + j]);
    float cp = __half2float(Zb[768 + j]);
    if (U) {
        const __half* Ub = U + (size_t)b * NU;
        fp += __half2float(Ub[j]);
        ip += __half2float(Ub[256 + j]);
        op += __half2float(Ub[512 + j]);
    }
    float fg = sigf(fp);
    float ig = sigf(ip);
    float og = sigf(op);
    float ct = tanhf_fast(cp + aux);

    size_t sidx = (size_t)b * SH + l * Hh + j;
    float cn = fg * c[sidx] + ig * ct;
    float hn = og * cn;
    c[sidx] = cn;
    __half hh = __float2half(hn);
    hsp[sidx] = hh;
    if (featf) featf[(size_t)b * FEATK + t * Hh + j] = hh;
}

// ---------------- small fp32 dot kernels ------------------------------------
__global__ void glog0_kernel(const float* __restrict__ x,
                             const float* __restrict__ wig,
                             const float* __restrict__ big,
                             float* __restrict__ G0)
{
    int gw = (blockIdx.x * blockDim.x + threadIdx.x) >> 5;
    int lane = threadIdx.x & 31;
    if (gw >= Bsz * 3) return;
    int b = gw / 3;
    int r = gw - b * 3;
    const float* xr = x + (size_t)b * Dd;
    const float* wr = wig + (size_t)r * Dd;
    float sum = 0.f;
#pragma unroll 4
    for (int k = lane; k < Dd; k += 32) sum += xr[k] * wr[k];
#pragma unroll
    for (int off = 16; off; off >>= 1) sum += __shfl_xor_sync(0xFFFFFFFFu, sum, off);
    if (lane == 0) G0[(size_t)b * 3 + r] = sum + big[r];
}

// ---------------- state init / splits --------------------------------------
__global__ void init_state(const float* __restrict__ hid, const float* __restrict__ cur,
                           __half* __restrict__ hsp, float* __restrict__ c)
{
    int i = blockIdx.x * blockDim.x + threadIdx.x;
    const int total = Ss * Bsz * Hh;
    if (i >= total) return;
    int l = i / (Bsz * Hh);
    int r = i - l * (Bsz * Hh);
    int b = r >> 8;
    int j = r & 255;
    size_t dst = (size_t)b * SH + l * Hh + j;
    hsp[dst] = __float2half(hid[i]);
    c[dst]   = cur[i];
}

__global__ void conv_x(const float* __restrict__ x, __half* __restrict__ xsp)
{
    int i = blockIdx.x * blockDim.x + threadIdx.x;
    if (i >= Bsz * Dd) return;
    xsp[i] = __float2half(x[i]);
}

// ---------------- fused weight repack (fp32 -> fp16, concat rows) ----------
#define RW1 (Ss * NZS * Dd)
#define RW2 (RW1 + NU * Hh)            // Whfio layer 0 only
#define RW3 (RW2 + NAG * SH)
#define RW4 (RW3 + Ss * NZS)
#define RW5 (RW4 + NU)                 // bhfio layer 0 only
#define RW6 (RW5 + NLP * FEATK)
#define RW7 (RW6 + 2 * NZS * KZU)      // WZU layers 1,2
#define RW8 (RW7 + 2 * NZS)            // biZU

__global__ void repack_all(const float* __restrict__ wif, const float* __restrict__ wii,
                           const float* __restrict__ wio, const float* __restrict__ wic,
                           const float* __restrict__ whf, const float* __restrict__ whi,
                           const float* __restrict__ who, const float* __restrict__ whc,
                           const float* __restrict__ bif, const float* __restrict__ bii,
                           const float* __restrict__ bio, const float* __restrict__ bic,
                           const float* __restrict__ bhf, const float* __restrict__ bhi,
                           const float* __restrict__ bho, const float* __restrict__ wlast,
                           __half* __restrict__ WiAll, __half* __restrict__ Whfio0,
                           __half* __restrict__ Whc, __half* __restrict__ Wlast,
                           __half* __restrict__ WZU,
                           float* __restrict__ biAll, float* __restrict__ bhfio0,
                           float* __restrict__ biZU)
{
    int idx = blockIdx.x * blockDim.x + threadIdx.x;
    if (idx < RW1) {
        int k = idx % Dd;
        int r = (idx / Dd) % NZS;
        int l = idx / (Dd * NZS);
        float v;
        if      (r < 256) v = wif[((size_t)l * Hh + r)       * Dd + k];
        else if (r < 512) v = wii[((size_t)l * Hh + r - 256) * Dd + k];
        else if (r < 768) v = wio[((size_t)l * Hh + r - 512) * Dd + k];
        else              v = wic[((size_t)l * Hh + r - 768) * Dd + k];
        WiAll[idx] = __float2half(v);
    } else if (idx < RW2) {
        int t = idx - RW1;
        int k = t % Hh;
        int r = t / Hh;
        float v;
        if      (r < 256) v = whf[(size_t)r * Hh + k];
        else if (r < 512) v = whi[(size_t)(r - 256) * Hh + k];
        else              v = who[(size_t)(r - 512) * Hh + k];
        Whfio0[t] = __float2half(v);
    } else if (idx < RW3) {
        int t = idx - RW2;
        Whc[t] = __float2half(whc[t]);
    } else if (idx < RW4) {
        int t = idx - RW3;
        int r = t % NZS, l = t / NZS;
        float v;
        if      (r < 256) v = bif[l * Hh + r];
        else if (r < 512) v = bii[l * Hh + r - 256];
        else if (r < 768) v = bio[l * Hh + r - 512];
        else              v = bic[l * Hh + r - 768];
        biAll[t] = v;
    } else if (idx < RW5) {
        int r = idx - RW4;
        float v;
        if      (r < 256) v = bhf[r];
        else if (r < 512) v = bhi[r - 256];
        else              v = bho[r - 512];
        bhfio0[r] = v;
    } else if (idx < RW6) {
        int t = idx - RW5;
        int r = t / FEATK;
        int k = t - r * FEATK;
        Wlast[t] = (r < OUTN) ? __float2half(wlast[(size_t)r * FEATK + k])
                              : __float2half(0.f);
    } else if (idx < RW7) {
        int t = idx - RW6;
        int k = t % KZU;
        int r = (t / KZU) % NZS;
        int lz = t / (KZU * NZS) + 1;       // 1 or 2
        float v = 0.f;
        if (k < 256) {
            if      (r < 256) v = wif[((size_t)lz * Hh + r)       * Dd + k];
            else if (r < 512) v = wii[((size_t)lz * Hh + r - 256) * Dd + k];
            else if (r < 768) v = wio[((size_t)lz * Hh + r - 512) * Dd + k];
            else              v = wic[((size_t)lz * Hh + r - 768) * Dd + k];
        } else {
            int kk = k - 256;
            if      (r < 256) v = whf[((size_t)lz * Hh + r)       * Hh + kk];
            else if (r < 512) v = whi[((size_t)lz * Hh + r - 256) * Hh + kk];
            else if (r < 768) v = who[((size_t)lz * Hh + r - 512) * Hh + kk];
            // c rows (r>=768): recurrent part zero
        }
        WZU[t] = __float2half(v);
    } else if (idx < RW8) {
        int t = idx - RW7;
        int r = t % NZS;
        int lz = t / NZS + 1;
        float v;
        if      (r < 256) v = bif[lz * Hh + r]       + bhf[lz * Hh + r];
        else if (r < 512) v = bii[lz * Hh + r - 256] + bhi[lz * Hh + r - 256];
        else if (r < 768) v = bio[lz * Hh + r - 512] + bho[lz * Hh + r - 512];
        else              v = bic[lz * Hh + r - 768];
        biZU[t] = v;
    }
}

// ---------------- orchestration --------------------------------------------
extern "C" void kernel_launch(void* const* d_in, const int* in_sizes, int n_in,
                              void* d_out, int out_size)
{
    (void)in_sizes; (void)n_in; (void)out_size;
    const float* x    = (const float*)d_in[0];
    const float* hid0 = (const float*)d_in[1];
    const float* cur0 = (const float*)d_in[2];
    const float* Wi_f = (const float*)d_in[3];
    const float* bi_f = (const float*)d_in[4];
    const float* Wi_i = (const float*)d_in[5];
    const float* bi_i = (const float*)d_in[6];
    const float* Wi_o = (const float*)d_in[7];
    const float* bi_o = (const float*)d_in[8];
    const float* Wi_c = (const float*)d_in[9];
    const float* bi_c = (const float*)d_in[10];
    const float* Wi_g = (const float*)d_in[11];
    const float* bi_g = (const float*)d_in[12];
    const float* Wh_f = (const float*)d_in[13];
    const float* bh_f = (const float*)d_in[14];
    const float* Wh_i = (const float*)d_in[15];
    const float* bh_i = (const float*)d_in[16];
    const float* Wh_o = (const float*)d_in[17];
    const float* bh_o = (const float*)d_in[18];
    const float* Wh_g = (const float*)d_in[19];
    const float* bh_g = (const float*)d_in[20];
    const float* Wh_c = (const float*)d_in[21];
    const float* bh_c = (const float*)d_in[22];
    const float* W_last = (const float*)d_in[23];
    const float* b_last = (const float*)d_in[24];
    float* out = (float*)d_out;

    __half *hsp, *xsp, *WiAll, *Whfio0, *Whc, *Wlast, *WZU, *U, *AG, *Z, *Z0, *featf;
    float *cst, *G2, *G0, *biAll, *bhfio0, *biZU;
    cudaGetSymbolAddress((void**)&hsp,    g_hsp);
    cudaGetSymbolAddress((void**)&xsp,    g_xsp);
    cudaGetSymbolAddress((void**)&cst,    g_c);
    cudaGetSymbolAddress((void**)&U,      g_U);
    cudaGetSymbolAddress((void**)&AG,     g_AG);
    cudaGetSymbolAddress((void**)&G2,     g_G2);
    cudaGetSymbolAddress((void**)&G0,     g_G0);
    cudaGetSymbolAddress((void**)&Z,      g_Z);
    cudaGetSymbolAddress((void**)&Z0,     g_Z0);
    cudaGetSymbolAddress((void**)&featf,  g_featf);
    cudaGetSymbolAddress((void**)&WiAll,  g_WiAll);
    cudaGetSymbolAddress((void**)&biAll,  g_biAll);
    cudaGetSymbolAddress((void**)&Whfio0, g_Whfio);
    cudaGetSymbolAddress((void**)&bhfio0, g_bhfio);
    cudaGetSymbolAddress((void**)&Whc,    g_Whc);
    cudaGetSymbolAddress((void**)&Wlast,  g_Wlast);
    cudaGetSymbolAddress((void**)&WZU,    g_WZU);
    cudaGetSymbolAddress((void**)&biZU,   g_biZU);

    cudaFuncSetAttribute(gemm256,  cudaFuncAttributeMaxDynamicSharedMemorySize, SMEM_GEMM);
    cudaFuncSetAttribute(gemm_agu, cudaFuncAttributeMaxDynamicSharedMemorySize, SMEM_GEMM);
    cudaFuncSetAttribute(gemm_out, cudaFuncAttributeMaxDynamicSharedMemorySize, SMEM_GEMM);

    const dim3 blk(256);

    cudaLaunchAttribute pat[1];
    pat[0].id = cudaLaunchAttributeProgrammaticStreamSerialization;
    pat[0].val.programmaticStreamSerializationAllowed = 1;
    auto mkcfg = [&](dim3 g, size_t sm) {
        cudaLaunchConfig_t cf;
        cf.gridDim = g;
        cf.blockDim = blk;
        cf.dynamicSmemBytes = sm;
        cf.stream = 0;
        cf.attrs = pat;
        cf.numAttrs = 1;
        return cf;
    };

    // ---- setup ----
    init_state<<<(Ss * Bsz * Hh + 255) / 256, blk>>>(hid0, cur0, hsp, cst);
    conv_x<<<(Bsz * Dd + 255) / 256, blk>>>(x, xsp);
    repack_all<<<(RW8 + 255) / 256, blk>>>(Wi_f, Wi_i, Wi_o, Wi_c,
                                           Wh_f, Wh_i, Wh_o, Wh_c,
                                           bi_f, bi_i, bi_o, bi_c,
                                           bh_f, bh_i, bh_o, W_last,
                                           WiAll, Whfio0, Whc, Wlast, WZU,
                                           biAll, bhfio0, biZU);
    glog0_kernel<<<(Bsz * 3 * 32 + 255) / 256, blk>>>(x, Wi_g, bi_g, G0);
    // Z0 = x @ Wi[0]^T + bias  (time-invariant)
    gemm256<<<dim3(4, 32, 1), blk, SMEM_GEMM>>>(xsp, Dd, WiAll, Dd,
                                                biAll, Z0, NZS, Dd);

    for (int t = 0; t < REPT; t++) {
        // AG + U0 + G2 (all read state(t-1))
        {
            cudaLaunchConfig_t cf = mkcfg(dim3(13, 32, 1), SMEM_GEMM);
            cudaLaunchKernelEx(&cf, gemm_agu,
                (const __half*)hsp, (const __half*)Whc, bh_c, AG,
                (const __half*)Whfio0, (const float*)bhfio0, U,
                Wh_g, bh_g, G2);
        }
        // cell0 (adds U0)
        {
            cudaLaunchConfig_t cf = mkcfg(dim3(Bsz), 0);
            cudaLaunchKernelEx(&cf, cell_kernel,
                (const __half*)Z0, (const __half*)U, (const __half*)AG,
                (const float*)G2, (const float*)G0,
                (const float*)nullptr, (const float*)nullptr, (const __half*)nullptr,
                hsp, cst, (__half*)nullptr, 0, t);
        }
        // ZU1 = [h0(t) | h1(t-1)] @ [Wi1 | Whfio1]^T + (bi1+bh1)
        {
            cudaLaunchConfig_t cf = mkcfg(dim3(4, 32, 1), SMEM_GEMM);
            cudaLaunchKernelEx(&cf, gemm256,
                (const __half*)hsp, (int)SH,
                (const __half*)WZU, (int)KZU,
                (const float*)biZU, Z, (int)NZS, (int)KZU);
        }
        // cell1 (Z contains Z+U)
        {
            cudaLaunchConfig_t cf = mkcfg(dim3(Bsz), 0);
            cudaLaunchKernelEx(&cf, cell_kernel,
                (const __half*)Z, (const __half*)nullptr,
                (const __half*)AG, (const float*)G2, (const float*)nullptr,
                (const float*)(Wi_g + (size_t)3 * Dd), (const float*)(bi_g + 3),
                (const __half*)hsp,
                hsp, cst, (__half*)nullptr, 1, t);
        }
        // ZU2 = [h1(t) | h2(t-1)] @ [Wi2 | Whfio2]^T + (bi2+bh2)
        {
            cudaLaunchConfig_t cf = mkcfg(dim3(4, 32, 1), SMEM_GEMM);
            cudaLaunchKernelEx(&cf, gemm256,
                (const __half*)(hsp + Hh), (int)SH,
                (const __half*)(WZU + (size_t)NZS * KZU), (int)KZU,
                (const float*)(biZU + NZS), Z, (int)NZS, (int)KZU);
        }
        // cell2 (Z contains Z+U)
        {
            __half* fptr = (t < REPT - 1) ? featf : nullptr;
            cudaLaunchConfig_t cf = mkcfg(dim3(Bsz), 0);
            cudaLaunchKernelEx(&cf, cell_kernel,
                (const __half*)Z, (const __half*)nullptr,
                (const __half*)AG, (const float*)G2, (const float*)nullptr,
                (const float*)(Wi_g + (size_t)6 * Dd), (const float*)(bi_g + 6),
                (const __half*)(hsp + Hh),
                hsp, cst, fptr, 2, t);
        }
    }

    // out = sigmoid(feat @ W_last^T + b_last) via HMMA GEMM (N padded to 256)
    {
        cudaLaunchConfig_t cf = mkcfg(dim3(1, 32, 1), SMEM_GEMM);
        cudaLaunchKernelEx(&cf, gemm_out,
            (const __half*)featf, (const __half*)Wlast, b_last, out);
    }
}